// round 3
// baseline (speedup 1.0000x reference)
#include <cuda_runtime.h>
#include <math.h>

// Problem constants
#define BTOT   1792          // N*D*H = 1*32*56
#define CH_STR 7168          // 128*56
#define XPLANE 100352        // 32*56*56 == BTOT*56
#define NQKV   100352.0
#define NSIM   5619712.0     // BTOT*56*56
#define EPSBN  1e-5f

// ---------------- scratch (device globals; no runtime alloc) ----------------
__device__ float g_qkv[BTOT * 128 * 56];   // [b][o][i]  o = g*16+cc (q:0-3,k:4-7,v:8-15)
__device__ float g_so [BTOT * 128 * 56];   // [b][o2][i]
__device__ double g_qsum[128], g_qsq[128];
__device__ double g_ssum[24],  g_ssq[24];
__device__ double g_osum[128], g_osq[128];
// precomputed relative-embedding moment tables
__device__ float g_SR[8][56];
__device__ float g_TQ[10][56];
__device__ float g_TK[10][56];

__constant__ int   c_PA[10] = {0,0,0,0,1,1,1,2,2,3};
__constant__ int   c_PB[10] = {0,1,2,3,1,2,3,2,3,3};
__constant__ float c_PW[10] = {1.f,2.f,2.f,2.f,1.f,2.f,2.f,1.f,2.f,1.f};

// ---------------- K_init: zero accumulators + prefix tables -----------------
__global__ void k_init(const float* __restrict__ relative) {
    __shared__ float rel[8][112];
    int t = threadIdx.x;
    if (t < 128) { g_qsum[t] = 0.0; g_qsq[t] = 0.0; g_osum[t] = 0.0; g_osq[t] = 0.0; }
    if (t < 24)  { g_ssum[t] = 0.0; g_ssq[t] = 0.0; }
    for (int idx = t; idx < 8 * 111; idx += 256)
        rel[idx / 111][idx % 111] = relative[idx];
    __syncthreads();
    for (int task = t; task < 448; task += 256) {
        int c = task / 56, i = task % 56;
        float s = 0.f;
        for (int d = 0; d < 56; ++d) s += rel[c][i + d];
        g_SR[c][i] = s;
    }
    for (int task = t; task < 1120; task += 256) {
        int p = task / 56, i = task % 56;
        int pp = p % 10; int isK = (p >= 10) ? 4 : 0;
        int a = c_PA[pp] + isK, bb = c_PB[pp] + isK;
        float s = 0.f;
        for (int d = 0; d < 56; ++d) s += rel[a][i + d] * rel[bb][i + d];
        s *= c_PW[pp];
        if (isK) g_TK[pp][i] = s; else g_TQ[pp][i] = s;
    }
}

// ---------------- K1: qkv = w @ x  (+ per-channel stats) --------------------
__global__ void __launch_bounds__(256) k_qkv(const float* __restrict__ x,
                                             const float* __restrict__ w) {
    __shared__ float xs[64][57];
    __shared__ float ws[128][65];
    const int b = blockIdx.x;
    for (int t = threadIdx.x; t < 64 * 56; t += 256) {
        int c = t / 56, i = t % 56;
        xs[c][i] = x[c * XPLANE + b * 56 + i];
    }
    for (int t = threadIdx.x; t < 128 * 64; t += 256)
        ws[t >> 6][t & 63] = w[t];
    __syncthreads();

    const int og = threadIdx.x >> 3;
    const int ig = threadIdx.x & 7;
    const int o0 = og * 4, i0 = ig * 7;
    float acc[4][7];
#pragma unroll
    for (int a = 0; a < 4; a++)
#pragma unroll
        for (int c2 = 0; c2 < 7; c2++) acc[a][c2] = 0.f;

    for (int c = 0; c < 64; ++c) {
        float w0 = ws[o0][c], w1 = ws[o0 + 1][c], w2 = ws[o0 + 2][c], w3 = ws[o0 + 3][c];
#pragma unroll
        for (int ii = 0; ii < 7; ++ii) {
            float xv = xs[c][i0 + ii];
            acc[0][ii] += w0 * xv; acc[1][ii] += w1 * xv;
            acc[2][ii] += w2 * xv; acc[3][ii] += w3 * xv;
        }
    }
    float* outb = g_qkv + (size_t)b * CH_STR;
#pragma unroll
    for (int oo = 0; oo < 4; ++oo) {
        float s = 0.f, sq = 0.f;
#pragma unroll
        for (int ii = 0; ii < 7; ++ii) {
            float v = acc[oo][ii];
            outb[(o0 + oo) * 56 + i0 + ii] = v;
            s += v; sq += v * v;
        }
        for (int off = 4; off; off >>= 1) {
            s  += __shfl_down_sync(0xffffffffu, s,  off);
            sq += __shfl_down_sync(0xffffffffu, sq, off);
        }
        if (ig == 0) {
            atomicAdd(&g_qsum[o0 + oo], (double)s);
            atomicAdd(&g_qsq [o0 + oo], (double)sq);
        }
    }
}

// ---------------- K2: analytic sim moments (folds qkv-BN finalize) ----------
__global__ void __launch_bounds__(256) k_mom(const float* __restrict__ qg,
                                             const float* __restrict__ qb) {
    __shared__ float sQs[128], sQo[128];
    const int b = blockIdx.x;
    {
        int o = threadIdx.x;
        if (o < 128) {
            double inv = 1.0 / NQKV;
            double m = g_qsum[o] * inv;
            double v = g_qsq[o] * inv - m * m;
            float sc = qg[o] * rsqrtf((float)v + EPSBN);
            sQs[o] = sc;
            sQo[o] = qb[o] - (float)m * sc;
        }
    }
    __syncthreads();

    const int g = threadIdx.x >> 5;
    const int lane = threadIdx.x & 31;
    const float* base = g_qkv + (size_t)b * CH_STR + g * 16 * 56;

    float part[32];
#pragma unroll
    for (int v = 0; v < 32; ++v) part[v] = 0.f;

#pragma unroll
    for (int ii = 0; ii < 2; ++ii) {
        int i = lane + ii * 32;
        if (i < 56) {
            float q[4], k[4];
#pragma unroll
            for (int c = 0; c < 4; ++c) {
                int oq = g * 16 + c, ok = g * 16 + 4 + c;
                q[c] = base[c * 56 + i]       * sQs[oq] + sQo[oq];
                k[c] = base[(4 + c) * 56 + i] * sQs[ok] + sQo[ok];
            }
#pragma unroll
            for (int c = 0; c < 4; ++c) {
                part[c]     += q[c];
                part[4 + c] += k[c];
                part[28] += q[c] * g_SR[c][i];
                part[30] += k[c] * g_SR[4 + c][i];
            }
#pragma unroll
            for (int p = 0; p < 10; ++p) {
                float pq = q[c_PA[p]] * q[c_PB[p]];
                float pk = k[c_PA[p]] * k[c_PB[p]];
                part[8 + p]  += pq;
                part[18 + p] += pk;
                part[29] += pq * g_TQ[p][i];
                part[31] += pk * g_TK[p][i];
            }
        }
    }
#pragma unroll
    for (int v = 0; v < 32; ++v)
        for (int off = 16; off; off >>= 1)
            part[v] += __shfl_down_sync(0xffffffffu, part[v], off);

    if (lane == 0) {
        float S1 = 0.f, S2 = 0.f;
#pragma unroll
        for (int c = 0; c < 4; ++c) S1 += part[c] * part[4 + c];
#pragma unroll
        for (int p = 0; p < 10; ++p) S2 += c_PW[p] * part[8 + p] * part[18 + p];
        atomicAdd(&g_ssum[g],      (double)S1);
        atomicAdd(&g_ssq [g],      (double)S2);
        atomicAdd(&g_ssum[8 + g],  (double)(0.1f  * part[28]));
        atomicAdd(&g_ssq [8 + g],  (double)(0.01f * part[29]));
        atomicAdd(&g_ssum[16 + g], (double)(0.1f  * part[30]));
        atomicAdd(&g_ssq [16 + g], (double)(0.01f * part[31]));
    }
}

// ---------------- K3: attention — 4x7 register tiles, diagonal rel reuse ----
// block = (b, g); 112 threads = 14 ti (4 i each) x 8 tj (7 j each)
__global__ void __launch_bounds__(112) k_attn(const float* __restrict__ relative,
                                              const float* __restrict__ qg,
                                              const float* __restrict__ qb,
                                              const float* __restrict__ sg,
                                              const float* __restrict__ sb) {
    __shared__ __align__(16) float qsT[56][4];
    __shared__ __align__(16) float ksT[56][4];
    __shared__ __align__(16) float vsT[56][8];
    __shared__ __align__(16) float relqT[111][4];
    __shared__ __align__(16) float relkT[111][4];
    __shared__ __align__(16) float relvT[111][12];
    __shared__ float rsum[8][57];
    __shared__ float rinv[56];
    __shared__ float pacc[8 * 56 * 9];        // [ch][i][tj(+pad)]
    __shared__ float SB[16][57];
    __shared__ float sQs[16], sQo[16], sC[4];

    const int b = blockIdx.x >> 3, g = blockIdx.x & 7;
    const int t = threadIdx.x;

    // folded finalizers: qkv-BN for this head's 16 channels + sim-BN coeffs
    if (t < 16) {
        int o = g * 16 + t;
        double inv = 1.0 / NQKV;
        double m = g_qsum[o] * inv;
        double v = g_qsq[o] * inv - m * m;
        float sc = qg[o] * rsqrtf((float)v + EPSBN);
        sQs[t] = sc;
        sQo[t] = qb[o] - (float)m * sc;
    }
    if (t == 16) {
        double inv = 1.0 / NSIM;
        float fac[3] = {1.f, 0.1f, 0.1f};
        float csum = 0.f;
        for (int r = 0; r < 3; ++r) {
            int idx = r * 8 + g;
            double m = g_ssum[idx] * inv;
            double v = g_ssq[idx] * inv - m * m;
            float aa = sg[idx] * rsqrtf((float)v + EPSBN);
            sC[r] = aa * fac[r];
            csum += sb[idx] - (float)m * aa;
        }
        sC[3] = csum;
    }
    __syncthreads();

    for (int idx = t; idx < 16 * 56; idx += 112) {
        int cc = idx / 56, i = idx % 56;
        float v = g_qkv[(size_t)b * CH_STR + (g * 16 + cc) * 56 + i] * sQs[cc] + sQo[cc];
        if (cc < 4) qsT[i][cc] = v;
        else if (cc < 8) ksT[i][cc - 4] = v;
        else vsT[i][cc - 8] = v;
    }
    for (int idx = t; idx < 16 * 111; idx += 112) {
        int c = idx / 111, d = idx % 111;
        float v = relative[idx];
        if (c < 4) relqT[d][c] = v;
        else if (c < 8) relkT[d][c - 4] = v;
        else relvT[d][c - 8] = v;
    }
    __syncthreads();

    const float cqk = sC[0], cqr = sC[1], ckr = sC[2], soff = sC[3];
    const int ti = t >> 3, tj = t & 7;
    const int i0 = ti * 4, j0 = tj * 7;
    const int D0 = i0 - j0 + 55;

    float4 q[4], kk[7];
#pragma unroll
    for (int ii = 0; ii < 4; ++ii) q[ii] = *(const float4*)qsT[i0 + ii];
#pragma unroll
    for (int jj = 0; jj < 7; ++jj) kk[jj] = *(const float4*)ksT[j0 + jj];

    // ---- phase 1: logits by diagonals (rel loads amortized) ----
    float P[28];
#pragma unroll
    for (int cc2 = 0; cc2 < 10; ++cc2) {
        const int c = cc2 - 6;
        float4 rq = *(const float4*)relqT[D0 + c];
        float4 rk = *(const float4*)relkT[110 - (D0 + c)];
#pragma unroll
        for (int ii = 0; ii < 4; ++ii) {
            int jj = ii - c;
            if (jj >= 0 && jj < 7) {
                float4 qi = q[ii], kj = kk[jj];
                float qk = qi.x * kj.x + qi.y * kj.y + qi.z * kj.z + qi.w * kj.w;
                float qr = qi.x * rq.x + qi.y * rq.y + qi.z * rq.z + qi.w * rq.w;
                float kr = kj.x * rk.x + kj.y * rk.y + kj.z * rk.z + kj.w * rk.w;
                P[ii * 7 + jj] = fmaf(cqk, qk, fmaf(cqr, qr, fmaf(ckr, kr, soff)));
            }
        }
    }

    // ---- phase 2: exp (no max: logits are BN-normalized, overflow-safe) ----
    {
        float rs[4] = {0.f, 0.f, 0.f, 0.f};
#pragma unroll
        for (int ii = 0; ii < 4; ++ii)
#pragma unroll
            for (int jj = 0; jj < 7; ++jj) {
                float p = __expf(P[ii * 7 + jj]);
                P[ii * 7 + jj] = p;
                rs[ii] += p;
            }
#pragma unroll
        for (int ii = 0; ii < 4; ++ii) rsum[tj][i0 + ii] = rs[ii];
    }
    __syncthreads();
    if (t < 56) {
        float s = 0.f;
#pragma unroll
        for (int w = 0; w < 8; ++w) s += rsum[w][t];
        rinv[t] = 1.0f / s;
    }

    // ---- phase 3a: sv partials ----
    {
        float av[32];
#pragma unroll
        for (int v = 0; v < 32; ++v) av[v] = 0.f;
#pragma unroll
        for (int jj = 0; jj < 7; ++jj) {
            float4 v0 = *(const float4*)&vsT[j0 + jj][0];
            float4 v1 = *(const float4*)&vsT[j0 + jj][4];
#pragma unroll
            for (int ii = 0; ii < 4; ++ii) {
                float p = P[ii * 7 + jj];
                av[0 * 4 + ii] += p * v0.x; av[1 * 4 + ii] += p * v0.y;
                av[2 * 4 + ii] += p * v0.z; av[3 * 4 + ii] += p * v0.w;
                av[4 * 4 + ii] += p * v1.x; av[5 * 4 + ii] += p * v1.y;
                av[6 * 4 + ii] += p * v1.z; av[7 * 4 + ii] += p * v1.w;
            }
        }
#pragma unroll
        for (int ch = 0; ch < 8; ++ch)
#pragma unroll
            for (int ii = 0; ii < 4; ++ii)
                pacc[(ch * 56 + i0 + ii) * 9 + tj] = av[ch * 4 + ii];
    }
    __syncthreads();
    // combine sv
#pragma unroll
    for (int r = 0; r < 4; ++r) {
        int e = t + r * 112;                   // 0..447
        int ch = e / 56, i = e % 56;
        const float* pp = &pacc[(ch * 56 + i) * 9];
        float s = pp[0] + pp[1] + pp[2] + pp[3] + pp[4] + pp[5] + pp[6] + pp[7];
        SB[2 * ch][i] = s * rinv[i];
    }
    __syncthreads();

    // ---- phase 3b: sve partials (diagonal rel reuse) ----
    {
        float av[32];
#pragma unroll
        for (int v = 0; v < 32; ++v) av[v] = 0.f;
#pragma unroll
        for (int cc2 = 0; cc2 < 10; ++cc2) {
            const int c = cc2 - 6;
            float4 r0 = *(const float4*)&relvT[D0 + c][0];
            float4 r1 = *(const float4*)&relvT[D0 + c][4];
#pragma unroll
            for (int ii = 0; ii < 4; ++ii) {
                int jj = ii - c;
                if (jj >= 0 && jj < 7) {
                    float p = P[ii * 7 + jj];
                    av[0 * 4 + ii] += p * r0.x; av[1 * 4 + ii] += p * r0.y;
                    av[2 * 4 + ii] += p * r0.z; av[3 * 4 + ii] += p * r0.w;
                    av[4 * 4 + ii] += p * r1.x; av[5 * 4 + ii] += p * r1.y;
                    av[6 * 4 + ii] += p * r1.z; av[7 * 4 + ii] += p * r1.w;
                }
            }
        }
#pragma unroll
        for (int ch = 0; ch < 8; ++ch)
#pragma unroll
            for (int ii = 0; ii < 4; ++ii)
                pacc[(ch * 56 + i0 + ii) * 9 + tj] = av[ch * 4 + ii];
    }
    __syncthreads();
    // combine sve
#pragma unroll
    for (int r = 0; r < 4; ++r) {
        int e = t + r * 112;
        int ch = e / 56, i = e % 56;
        const float* pp = &pacc[(ch * 56 + i) * 9];
        float s = pp[0] + pp[1] + pp[2] + pp[3] + pp[4] + pp[5] + pp[6] + pp[7];
        SB[2 * ch + 1][i] = s * rinv[i] * 0.1f;
    }
    __syncthreads();

    // ---- write g_so + per-channel out stats ----
    float* ob = g_so + (size_t)b * CH_STR + g * 16 * 56;
    for (int idx = t; idx < 16 * 56; idx += 112)
        ob[idx] = SB[idx / 56][idx % 56];
    if (t < 32) {
        int row = t >> 1, which = t & 1;
        float s = 0.f;
        for (int i2 = 0; i2 < 56; ++i2) {
            float v = SB[row][i2];
            s += which ? v * v : v;
        }
        if (which) atomicAdd(&g_osq [g * 16 + row], (double)s);
        else       atomicAdd(&g_osum[g * 16 + row], (double)s);
    }
}

// ---------------- K4: out BN (folded finalize) + pair-sum + layout ----------
__global__ void __launch_bounds__(256) k_out(float* __restrict__ out,
                                             const float* __restrict__ og,
                                             const float* __restrict__ ob) {
    __shared__ float sOs[128], sOo[128];
    {
        int o = threadIdx.x;
        if (o < 128) {
            double inv = 1.0 / NQKV;
            double m = g_osum[o] * inv;
            double v = g_osq[o] * inv - m * m;
            float sc = og[o] * rsqrtf((float)v + EPSBN);
            sOs[o] = sc;
            sOo[o] = ob[o] - (float)m * sc;
        }
    }
    __syncthreads();
    int idx = blockIdx.x * 256 + threadIdx.x;
    if (idx >= 1605632) return;
    int e  = idx * 4;
    int cp = e / XPLANE;
    int r  = e % XPLANE;
    int bq = r / 56, i = r % 56;
    const float* base = g_so + (size_t)bq * CH_STR + (2 * cp) * 56 + i;
    float4 s0 = *(const float4*)base;
    float4 s1 = *(const float4*)(base + 56);
    float sc0 = sOs[2 * cp], of0 = sOo[2 * cp];
    float sc1 = sOs[2 * cp + 1], of1 = sOo[2 * cp + 1];
    float4 o4;
    o4.x = s0.x * sc0 + of0 + s1.x * sc1 + of1;
    o4.y = s0.y * sc0 + of0 + s1.y * sc1 + of1;
    o4.z = s0.z * sc0 + of0 + s1.z * sc1 + of1;
    o4.w = s0.w * sc0 + of0 + s1.w * sc1 + of1;
    *(float4*)&out[e] = o4;
}

// ---------------- launch -----------------------------------------------------
extern "C" void kernel_launch(void* const* d_in, const int* in_sizes, int n_in,
                              void* d_out, int out_size) {
    const float* x        = (const float*)d_in[0];
    const float* w_qkv    = (const float*)d_in[1];
    const float* relative = (const float*)d_in[2];
    const float* qg       = (const float*)d_in[3];
    const float* qb       = (const float*)d_in[4];
    const float* sg       = (const float*)d_in[5];
    const float* sb       = (const float*)d_in[6];
    const float* og       = (const float*)d_in[7];
    const float* ob       = (const float*)d_in[8];
    float* out            = (float*)d_out;

    k_init <<<1, 256>>>(relative);
    k_qkv  <<<BTOT, 256>>>(x, w_qkv);
    k_mom  <<<BTOT, 256>>>(qg, qb);
    k_attn <<<BTOT * 8, 112>>>(relative, qg, qb, sg, sb);
    k_out  <<<6272, 256>>>(out, og, ob);
}

// round 4
// speedup vs baseline: 1.0239x; 1.0239x over previous
#include <cuda_runtime.h>
#include <math.h>

// Problem constants
#define BTOT   1792          // N*D*H = 1*32*56
#define CH_STR 7168          // 128*56
#define XPLANE 100352        // 32*56*56 == BTOT*56
#define NQKV   100352.0
#define NSIM   5619712.0     // BTOT*56*56
#define EPSBN  1e-5f

// ---------------- scratch (device globals; no runtime alloc) ----------------
__device__ float g_qkv[BTOT * 128 * 56];   // [b][o][i]  o = g*16+cc (q:0-3,k:4-7,v:8-15)
__device__ float g_so [BTOT * 128 * 56];   // [b][o2][i]
__device__ double g_qsum[128], g_qsq[128];
__device__ double g_ssum[24],  g_ssq[24];
__device__ double g_osum[128], g_osq[128];
// precomputed relative-embedding moment tables
__device__ float g_SR[8][56];
__device__ float g_TQ[10][56];
__device__ float g_TK[10][56];

__constant__ int   c_PA[10] = {0,0,0,0,1,1,1,2,2,3};
__constant__ int   c_PB[10] = {0,1,2,3,1,2,3,2,3,3};
__constant__ float c_PW[10] = {1.f,2.f,2.f,2.f,1.f,2.f,2.f,1.f,2.f,1.f};

// ---------------- K_init: zero accumulators + prefix tables -----------------
__global__ void k_init(const float* __restrict__ relative) {
    __shared__ float rel[8][112];
    int t = threadIdx.x;
    if (t < 128) { g_qsum[t] = 0.0; g_qsq[t] = 0.0; g_osum[t] = 0.0; g_osq[t] = 0.0; }
    if (t < 24)  { g_ssum[t] = 0.0; g_ssq[t] = 0.0; }
    for (int idx = t; idx < 8 * 111; idx += 256)
        rel[idx / 111][idx % 111] = relative[idx];
    __syncthreads();
    for (int task = t; task < 448; task += 256) {
        int c = task / 56, i = task % 56;
        float s = 0.f;
        for (int d = 0; d < 56; ++d) s += rel[c][i + d];
        g_SR[c][i] = s;
    }
    for (int task = t; task < 1120; task += 256) {
        int p = task / 56, i = task % 56;
        int pp = p % 10; int isK = (p >= 10) ? 4 : 0;
        int a = c_PA[pp] + isK, bb = c_PB[pp] + isK;
        float s = 0.f;
        for (int d = 0; d < 56; ++d) s += rel[a][i + d] * rel[bb][i + d];
        s *= c_PW[pp];
        if (isK) g_TK[pp][i] = s; else g_TQ[pp][i] = s;
    }
}

// ---------------- K1: qkv = w @ x  (+ per-channel stats) --------------------
__global__ void __launch_bounds__(256) k_qkv(const float* __restrict__ x,
                                             const float* __restrict__ w) {
    __shared__ float xs[64][57];
    __shared__ float ws[128][65];
    const int b = blockIdx.x;
    for (int t = threadIdx.x; t < 64 * 56; t += 256) {
        int c = t / 56, i = t % 56;
        xs[c][i] = x[c * XPLANE + b * 56 + i];
    }
    for (int t = threadIdx.x; t < 128 * 64; t += 256)
        ws[t >> 6][t & 63] = w[t];
    __syncthreads();

    const int og = threadIdx.x >> 3;
    const int ig = threadIdx.x & 7;
    const int o0 = og * 4, i0 = ig * 7;
    float acc[4][7];
#pragma unroll
    for (int a = 0; a < 4; a++)
#pragma unroll
        for (int c2 = 0; c2 < 7; c2++) acc[a][c2] = 0.f;

    for (int c = 0; c < 64; ++c) {
        float w0 = ws[o0][c], w1 = ws[o0 + 1][c], w2 = ws[o0 + 2][c], w3 = ws[o0 + 3][c];
#pragma unroll
        for (int ii = 0; ii < 7; ++ii) {
            float xv = xs[c][i0 + ii];
            acc[0][ii] += w0 * xv; acc[1][ii] += w1 * xv;
            acc[2][ii] += w2 * xv; acc[3][ii] += w3 * xv;
        }
    }
    float* outb = g_qkv + (size_t)b * CH_STR;
#pragma unroll
    for (int oo = 0; oo < 4; ++oo) {
        float s = 0.f, sq = 0.f;
#pragma unroll
        for (int ii = 0; ii < 7; ++ii) {
            float v = acc[oo][ii];
            outb[(o0 + oo) * 56 + i0 + ii] = v;
            s += v; sq += v * v;
        }
        for (int off = 4; off; off >>= 1) {
            s  += __shfl_down_sync(0xffffffffu, s,  off);
            sq += __shfl_down_sync(0xffffffffu, sq, off);
        }
        if (ig == 0) {
            atomicAdd(&g_qsum[o0 + oo], (double)s);
            atomicAdd(&g_qsq [o0 + oo], (double)sq);
        }
    }
}

// ---------------- K2: analytic sim moments (folds qkv-BN finalize) ----------
__global__ void __launch_bounds__(256) k_mom(const float* __restrict__ qg,
                                             const float* __restrict__ qb) {
    __shared__ float sQs[128], sQo[128];
    const int b = blockIdx.x;
    {
        int o = threadIdx.x;
        if (o < 128) {
            double inv = 1.0 / NQKV;
            double m = g_qsum[o] * inv;
            double v = g_qsq[o] * inv - m * m;
            float sc = qg[o] * rsqrtf((float)v + EPSBN);
            sQs[o] = sc;
            sQo[o] = qb[o] - (float)m * sc;
        }
    }
    __syncthreads();

    const int g = threadIdx.x >> 5;
    const int lane = threadIdx.x & 31;
    const float* base = g_qkv + (size_t)b * CH_STR + g * 16 * 56;

    float part[32];
#pragma unroll
    for (int v = 0; v < 32; ++v) part[v] = 0.f;

#pragma unroll
    for (int ii = 0; ii < 2; ++ii) {
        int i = lane + ii * 32;
        if (i < 56) {
            float q[4], k[4];
#pragma unroll
            for (int c = 0; c < 4; ++c) {
                int oq = g * 16 + c, ok = g * 16 + 4 + c;
                q[c] = base[c * 56 + i]       * sQs[oq] + sQo[oq];
                k[c] = base[(4 + c) * 56 + i] * sQs[ok] + sQo[ok];
            }
#pragma unroll
            for (int c = 0; c < 4; ++c) {
                part[c]     += q[c];
                part[4 + c] += k[c];
                part[28] += q[c] * g_SR[c][i];
                part[30] += k[c] * g_SR[4 + c][i];
            }
#pragma unroll
            for (int p = 0; p < 10; ++p) {
                float pq = q[c_PA[p]] * q[c_PB[p]];
                float pk = k[c_PA[p]] * k[c_PB[p]];
                part[8 + p]  += pq;
                part[18 + p] += pk;
                part[29] += pq * g_TQ[p][i];
                part[31] += pk * g_TK[p][i];
            }
        }
    }
#pragma unroll
    for (int v = 0; v < 32; ++v)
        for (int off = 16; off; off >>= 1)
            part[v] += __shfl_down_sync(0xffffffffu, part[v], off);

    if (lane == 0) {
        float S1 = 0.f, S2 = 0.f;
#pragma unroll
        for (int c = 0; c < 4; ++c) S1 += part[c] * part[4 + c];
#pragma unroll
        for (int p = 0; p < 10; ++p) S2 += c_PW[p] * part[8 + p] * part[18 + p];
        atomicAdd(&g_ssum[g],      (double)S1);
        atomicAdd(&g_ssq [g],      (double)S2);
        atomicAdd(&g_ssum[8 + g],  (double)(0.1f  * part[28]));
        atomicAdd(&g_ssq [8 + g],  (double)(0.01f * part[29]));
        atomicAdd(&g_ssum[16 + g], (double)(0.1f  * part[30]));
        atomicAdd(&g_ssq [16 + g], (double)(0.01f * part[31]));
    }
}

// ---------------- K3: attention — 2i x 7j tiles, 224 threads, rolling-k -----
// block = (b, g); thread (ti, tj): ti = t>>3 (0..27, rows 2ti,2ti+1),
//                                  tj = t&7  (0..7, cols 7tj..7tj+6)
__global__ void __launch_bounds__(224) k_attn(const float* __restrict__ relative,
                                              const float* __restrict__ qg,
                                              const float* __restrict__ qb,
                                              const float* __restrict__ sg,
                                              const float* __restrict__ sb) {
    __shared__ __align__(16) float qsT[56][4];
    __shared__ __align__(16) float ksT[56][4];
    __shared__ __align__(16) float vsT[56][8];
    __shared__ __align__(16) float relqT[111][4];
    __shared__ __align__(16) float relkT[111][4];
    __shared__ __align__(16) float relvT[111][12];
    __shared__ float rsum[8][57];
    __shared__ float rinv[56];
    __shared__ float pacc[8 * 56 * 9];        // [ch][i][tj(+pad)]
    __shared__ float SB[16][57];
    __shared__ float sQs[16], sQo[16], sC[4];

    const int b = blockIdx.x >> 3, g = blockIdx.x & 7;
    const int t = threadIdx.x;

    // folded finalizers
    if (t < 16) {
        int o = g * 16 + t;
        double inv = 1.0 / NQKV;
        double m = g_qsum[o] * inv;
        double v = g_qsq[o] * inv - m * m;
        float sc = qg[o] * rsqrtf((float)v + EPSBN);
        sQs[t] = sc;
        sQo[t] = qb[o] - (float)m * sc;
    }
    if (t == 16) {
        double inv = 1.0 / NSIM;
        float fac[3] = {1.f, 0.1f, 0.1f};
        float csum = 0.f;
        for (int r = 0; r < 3; ++r) {
            int idx = r * 8 + g;
            double m = g_ssum[idx] * inv;
            double v = g_ssq[idx] * inv - m * m;
            float aa = sg[idx] * rsqrtf((float)v + EPSBN);
            sC[r] = aa * fac[r];
            csum += sb[idx] - (float)m * aa;
        }
        sC[3] = csum;
    }
    __syncthreads();

    for (int idx = t; idx < 16 * 56; idx += 224) {
        int cc = idx / 56, i = idx % 56;
        float v = g_qkv[(size_t)b * CH_STR + (g * 16 + cc) * 56 + i] * sQs[cc] + sQo[cc];
        if (cc < 4) qsT[i][cc] = v;
        else if (cc < 8) ksT[i][cc - 4] = v;
        else vsT[i][cc - 8] = v;
    }
    for (int idx = t; idx < 16 * 111; idx += 224) {
        int c = idx / 111, d = idx % 111;
        float v = relative[idx];
        if (c < 4) relqT[d][c] = v;
        else if (c < 8) relkT[d][c - 4] = v;
        else relvT[d][c - 8] = v;
    }
    __syncthreads();

    const float cqk = sC[0], cqr = sC[1], ckr = sC[2], soff = sC[3];
    const int ti = t >> 3, tj = t & 7;
    const int i0 = ti * 2, j0 = tj * 7;
    const int dbase = i0 - j0 + 49;           // min diagonal in tile; 8 diagonals total

    float4 q0v = *(const float4*)qsT[i0];
    float4 q1v = *(const float4*)qsT[i0 + 1];

    // ---- phase 1: logits by diagonals, rolling k ----
    float P[14];
    {
        float4 kcur, kprev;
#pragma unroll
        for (int cc = 0; cc < 8; ++cc) {
            int d = dbase + cc;
            float4 rq = *(const float4*)relqT[d];
            float4 rk = *(const float4*)relkT[110 - d];
            if (cc <= 6) {                     // compile-time (unrolled)
                kcur = *(const float4*)ksT[j0 + 6 - cc];
                float qk = q0v.x * kcur.x + q0v.y * kcur.y + q0v.z * kcur.z + q0v.w * kcur.w;
                float qr = q0v.x * rq.x + q0v.y * rq.y + q0v.z * rq.z + q0v.w * rq.w;
                float kr = kcur.x * rk.x + kcur.y * rk.y + kcur.z * rk.z + kcur.w * rk.w;
                P[6 - cc] = fmaf(cqk, qk, fmaf(cqr, qr, fmaf(ckr, kr, soff)));
            }
            if (cc >= 1) {                     // row i0+1, j = j0 + 7 - cc, k = kprev
                float qk = q1v.x * kprev.x + q1v.y * kprev.y + q1v.z * kprev.z + q1v.w * kprev.w;
                float qr = q1v.x * rq.x + q1v.y * rq.y + q1v.z * rq.z + q1v.w * rq.w;
                float kr = kprev.x * rk.x + kprev.y * rk.y + kprev.z * rk.z + kprev.w * rk.w;
                P[7 + 7 - cc] = fmaf(cqk, qk, fmaf(cqr, qr, fmaf(ckr, kr, soff)));
            }
            kprev = kcur;
        }
    }

    // ---- phase 2: exp (no max; logits BN-normalized, overflow-safe) ----
    {
        float rs0 = 0.f, rs1 = 0.f;
#pragma unroll
        for (int jj = 0; jj < 7; ++jj) {
            float p0 = __expf(P[jj]);
            float p1 = __expf(P[7 + jj]);
            P[jj] = p0; P[7 + jj] = p1;
            rs0 += p0; rs1 += p1;
        }
        rsum[tj][i0] = rs0;
        rsum[tj][i0 + 1] = rs1;
    }
    __syncthreads();
    if (t < 56) {
        float s = 0.f;
#pragma unroll
        for (int w = 0; w < 8; ++w) s += rsum[w][t];
        rinv[t] = 1.0f / s;
    }

    // ---- phase 3a: sv partials (v shared across both rows) ----
    {
        float av[16];
#pragma unroll
        for (int v = 0; v < 16; ++v) av[v] = 0.f;
#pragma unroll
        for (int jj = 0; jj < 7; ++jj) {
            float4 v0 = *(const float4*)&vsT[j0 + jj][0];
            float4 v1 = *(const float4*)&vsT[j0 + jj][4];
            float p0 = P[jj], p1 = P[7 + jj];
            av[0] += p0 * v0.x; av[1] += p1 * v0.x;
            av[2] += p0 * v0.y; av[3] += p1 * v0.y;
            av[4] += p0 * v0.z; av[5] += p1 * v0.z;
            av[6] += p0 * v0.w; av[7] += p1 * v0.w;
            av[8]  += p0 * v1.x; av[9]  += p1 * v1.x;
            av[10] += p0 * v1.y; av[11] += p1 * v1.y;
            av[12] += p0 * v1.z; av[13] += p1 * v1.z;
            av[14] += p0 * v1.w; av[15] += p1 * v1.w;
        }
#pragma unroll
        for (int ch = 0; ch < 8; ++ch) {
            pacc[(ch * 56 + i0) * 9 + tj]     = av[ch * 2];
            pacc[(ch * 56 + i0 + 1) * 9 + tj] = av[ch * 2 + 1];
        }
    }
    __syncthreads();
#pragma unroll
    for (int r = 0; r < 2; ++r) {
        int e = t + r * 224;                   // 0..447
        int ch = e / 56, i = e % 56;
        const float* pp = &pacc[(ch * 56 + i) * 9];
        float s = pp[0] + pp[1] + pp[2] + pp[3] + pp[4] + pp[5] + pp[6] + pp[7];
        SB[2 * ch][i] = s * rinv[i];
    }
    __syncthreads();

    // ---- phase 3b: sve partials (diagonal rel reuse) ----
    {
        float av[16];
#pragma unroll
        for (int v = 0; v < 16; ++v) av[v] = 0.f;
#pragma unroll
        for (int cc = 0; cc < 8; ++cc) {
            int d = dbase + cc;
            float4 r0 = *(const float4*)&relvT[d][0];
            float4 r1 = *(const float4*)&relvT[d][4];
            if (cc <= 6) {                     // row i0, jj = 6-cc
                float p = P[6 - cc];
                av[0] += p * r0.x; av[2] += p * r0.y; av[4]  += p * r0.z; av[6]  += p * r0.w;
                av[8] += p * r1.x; av[10] += p * r1.y; av[12] += p * r1.z; av[14] += p * r1.w;
            }
            if (cc >= 1) {                     // row i0+1, jj = 7-cc
                float p = P[7 + 7 - cc];
                av[1] += p * r0.x; av[3] += p * r0.y; av[5]  += p * r0.z; av[7]  += p * r0.w;
                av[9] += p * r1.x; av[11] += p * r1.y; av[13] += p * r1.z; av[15] += p * r1.w;
            }
        }
#pragma unroll
        for (int ch = 0; ch < 8; ++ch) {
            pacc[(ch * 56 + i0) * 9 + tj]     = av[ch * 2];
            pacc[(ch * 56 + i0 + 1) * 9 + tj] = av[ch * 2 + 1];
        }
    }
    __syncthreads();
#pragma unroll
    for (int r = 0; r < 2; ++r) {
        int e = t + r * 224;
        int ch = e / 56, i = e % 56;
        const float* pp = &pacc[(ch * 56 + i) * 9];
        float s = pp[0] + pp[1] + pp[2] + pp[3] + pp[4] + pp[5] + pp[6] + pp[7];
        SB[2 * ch + 1][i] = s * rinv[i] * 0.1f;
    }
    __syncthreads();

    // ---- write g_so + per-channel out stats ----
    float* ob = g_so + (size_t)b * CH_STR + g * 16 * 56;
    for (int idx = t; idx < 16 * 56; idx += 224)
        ob[idx] = SB[idx / 56][idx % 56];
    if (t < 32) {
        int row = t >> 1, which = t & 1;
        float s = 0.f;
        for (int i2 = 0; i2 < 56; ++i2) {
            float v = SB[row][i2];
            s += which ? v * v : v;
        }
        if (which) atomicAdd(&g_osq [g * 16 + row], (double)s);
        else       atomicAdd(&g_osum[g * 16 + row], (double)s);
    }
}

// ---------------- K4: out BN (folded finalize) + pair-sum + layout ----------
__global__ void __launch_bounds__(256) k_out(float* __restrict__ out,
                                             const float* __restrict__ og,
                                             const float* __restrict__ ob) {
    __shared__ float sOs[128], sOo[128];
    {
        int o = threadIdx.x;
        if (o < 128) {
            double inv = 1.0 / NQKV;
            double m = g_osum[o] * inv;
            double v = g_osq[o] * inv - m * m;
            float sc = og[o] * rsqrtf((float)v + EPSBN);
            sOs[o] = sc;
            sOo[o] = ob[o] - (float)m * sc;
        }
    }
    __syncthreads();
    int idx = blockIdx.x * 256 + threadIdx.x;
    if (idx >= 1605632) return;
    int e  = idx * 4;
    int cp = e / XPLANE;
    int r  = e % XPLANE;
    int bq = r / 56, i = r % 56;
    const float* base = g_so + (size_t)bq * CH_STR + (2 * cp) * 56 + i;
    float4 s0 = *(const float4*)base;
    float4 s1 = *(const float4*)(base + 56);
    float sc0 = sOs[2 * cp], of0 = sOo[2 * cp];
    float sc1 = sOs[2 * cp + 1], of1 = sOo[2 * cp + 1];
    float4 o4;
    o4.x = s0.x * sc0 + of0 + s1.x * sc1 + of1;
    o4.y = s0.y * sc0 + of0 + s1.y * sc1 + of1;
    o4.z = s0.z * sc0 + of0 + s1.z * sc1 + of1;
    o4.w = s0.w * sc0 + of0 + s1.w * sc1 + of1;
    *(float4*)&out[e] = o4;
}

// ---------------- launch -----------------------------------------------------
extern "C" void kernel_launch(void* const* d_in, const int* in_sizes, int n_in,
                              void* d_out, int out_size) {
    const float* x        = (const float*)d_in[0];
    const float* w_qkv    = (const float*)d_in[1];
    const float* relative = (const float*)d_in[2];
    const float* qg       = (const float*)d_in[3];
    const float* qb       = (const float*)d_in[4];
    const float* sg       = (const float*)d_in[5];
    const float* sb       = (const float*)d_in[6];
    const float* og       = (const float*)d_in[7];
    const float* ob       = (const float*)d_in[8];
    float* out            = (float*)d_out;

    k_init <<<1, 256>>>(relative);
    k_qkv  <<<BTOT, 256>>>(x, w_qkv);
    k_mom  <<<BTOT, 256>>>(qg, qb);
    k_attn <<<BTOT * 8, 224>>>(relative, qg, qb, sg, sb);
    k_out  <<<6272, 256>>>(out, og, ob);
}

// round 6
// speedup vs baseline: 1.1297x; 1.1033x over previous
#include <cuda_runtime.h>
#include <math.h>

// Problem constants
#define BTOT   1792          // N*D*H = 1*32*56
#define CH_STR 7168          // 128*56
#define XPLANE 100352        // 32*56*56 == BTOT*56
#define NQKV   100352.0
#define NSIM   5619712.0     // BTOT*56*56
#define EPSBN  1e-5f

// ---------------- scratch (device globals; no runtime alloc) ----------------
__device__ float g_qkv[BTOT * 128 * 56];   // [b][o][i]  o = g*16+cc (q:0-3,k:4-7,v:8-15)
__device__ float g_so [BTOT * 128 * 56];   // [b][o2][i]
__device__ double g_qsum[128], g_qsq[128];
__device__ double g_ssum[24],  g_ssq[24];
__device__ double g_osum[128], g_osq[128];
// precomputed relative-embedding moment tables
__device__ float g_SR[8][56];
__device__ float g_TQ[10][56];
__device__ float g_TK[10][56];

__constant__ int   c_PA[10] = {0,0,0,0,1,1,1,2,2,3};
__constant__ int   c_PB[10] = {0,1,2,3,1,2,3,2,3,3};
__constant__ float c_PW[10] = {1.f,2.f,2.f,2.f,1.f,2.f,2.f,1.f,2.f,1.f};

// ---------------- K_init: zero accumulators + prefix tables -----------------
__global__ void k_init(const float* __restrict__ relative) {
    __shared__ float rel[8][112];
    int t = threadIdx.x;
    if (t < 128) { g_qsum[t] = 0.0; g_qsq[t] = 0.0; g_osum[t] = 0.0; g_osq[t] = 0.0; }
    if (t < 24)  { g_ssum[t] = 0.0; g_ssq[t] = 0.0; }
    for (int idx = t; idx < 8 * 111; idx += 256)
        rel[idx / 111][idx % 111] = relative[idx];
    __syncthreads();
    for (int task = t; task < 448; task += 256) {
        int c = task / 56, i = task % 56;
        float s = 0.f;
        for (int d = 0; d < 56; ++d) s += rel[c][i + d];
        g_SR[c][i] = s;
    }
    for (int task = t; task < 1120; task += 256) {
        int p = task / 56, i = task % 56;
        int pp = p % 10; int isK = (p >= 10) ? 4 : 0;
        int a = c_PA[pp] + isK, bb = c_PB[pp] + isK;
        float s = 0.f;
        for (int d = 0; d < 56; ++d) s += rel[a][i + d] * rel[bb][i + d];
        s *= c_PW[pp];
        if (isK) g_TK[pp][i] = s; else g_TQ[pp][i] = s;
    }
}

// ---------------- K1: qkv = w @ x  (+ per-channel stats) --------------------
__global__ void __launch_bounds__(256) k_qkv(const float* __restrict__ x,
                                             const float* __restrict__ w) {
    __shared__ float xs[64][57];
    __shared__ float ws[128][65];
    const int b = blockIdx.x;
    for (int t = threadIdx.x; t < 64 * 56; t += 256) {
        int c = t / 56, i = t % 56;
        xs[c][i] = x[c * XPLANE + b * 56 + i];
    }
    for (int t = threadIdx.x; t < 128 * 64; t += 256)
        ws[t >> 6][t & 63] = w[t];
    __syncthreads();

    const int og = threadIdx.x >> 3;
    const int ig = threadIdx.x & 7;
    const int o0 = og * 4, i0 = ig * 7;
    float acc[4][7];
#pragma unroll
    for (int a = 0; a < 4; a++)
#pragma unroll
        for (int c2 = 0; c2 < 7; c2++) acc[a][c2] = 0.f;

    for (int c = 0; c < 64; ++c) {
        float w0 = ws[o0][c], w1 = ws[o0 + 1][c], w2 = ws[o0 + 2][c], w3 = ws[o0 + 3][c];
#pragma unroll
        for (int ii = 0; ii < 7; ++ii) {
            float xv = xs[c][i0 + ii];
            acc[0][ii] += w0 * xv; acc[1][ii] += w1 * xv;
            acc[2][ii] += w2 * xv; acc[3][ii] += w3 * xv;
        }
    }
    float* outb = g_qkv + (size_t)b * CH_STR;
#pragma unroll
    for (int oo = 0; oo < 4; ++oo) {
        float s = 0.f, sq = 0.f;
#pragma unroll
        for (int ii = 0; ii < 7; ++ii) {
            float v = acc[oo][ii];
            outb[(o0 + oo) * 56 + i0 + ii] = v;
            s += v; sq += v * v;
        }
        for (int off = 4; off; off >>= 1) {
            s  += __shfl_down_sync(0xffffffffu, s,  off);
            sq += __shfl_down_sync(0xffffffffu, sq, off);
        }
        if (ig == 0) {
            atomicAdd(&g_qsum[o0 + oo], (double)s);
            atomicAdd(&g_qsq [o0 + oo], (double)sq);
        }
    }
}

// ---------------- K2: analytic sim moments (folds qkv-BN finalize) ----------
__global__ void __launch_bounds__(256) k_mom(const float* __restrict__ qg,
                                             const float* __restrict__ qb) {
    __shared__ float sQs[128], sQo[128];
    const int b = blockIdx.x;
    {
        int o = threadIdx.x;
        if (o < 128) {
            double inv = 1.0 / NQKV;
            double m = g_qsum[o] * inv;
            double v = g_qsq[o] * inv - m * m;
            float sc = qg[o] * rsqrtf((float)v + EPSBN);
            sQs[o] = sc;
            sQo[o] = qb[o] - (float)m * sc;
        }
    }
    __syncthreads();

    const int g = threadIdx.x >> 5;
    const int lane = threadIdx.x & 31;
    const float* base = g_qkv + (size_t)b * CH_STR + g * 16 * 56;

    float part[32];
#pragma unroll
    for (int v = 0; v < 32; ++v) part[v] = 0.f;

#pragma unroll
    for (int ii = 0; ii < 2; ++ii) {
        int i = lane + ii * 32;
        if (i < 56) {
            float q[4], k[4];
#pragma unroll
            for (int c = 0; c < 4; ++c) {
                int oq = g * 16 + c, ok = g * 16 + 4 + c;
                q[c] = base[c * 56 + i]       * sQs[oq] + sQo[oq];
                k[c] = base[(4 + c) * 56 + i] * sQs[ok] + sQo[ok];
            }
#pragma unroll
            for (int c = 0; c < 4; ++c) {
                part[c]     += q[c];
                part[4 + c] += k[c];
                part[28] += q[c] * g_SR[c][i];
                part[30] += k[c] * g_SR[4 + c][i];
            }
#pragma unroll
            for (int p = 0; p < 10; ++p) {
                float pq = q[c_PA[p]] * q[c_PB[p]];
                float pk = k[c_PA[p]] * k[c_PB[p]];
                part[8 + p]  += pq;
                part[18 + p] += pk;
                part[29] += pq * g_TQ[p][i];
                part[31] += pk * g_TK[p][i];
            }
        }
    }
#pragma unroll
    for (int v = 0; v < 32; ++v)
        for (int off = 16; off; off >>= 1)
            part[v] += __shfl_down_sync(0xffffffffu, part[v], off);

    if (lane == 0) {
        float S1 = 0.f, S2 = 0.f;
#pragma unroll
        for (int c = 0; c < 4; ++c) S1 += part[c] * part[4 + c];
#pragma unroll
        for (int p = 0; p < 10; ++p) S2 += c_PW[p] * part[8 + p] * part[18 + p];
        atomicAdd(&g_ssum[g],      (double)S1);
        atomicAdd(&g_ssq [g],      (double)S2);
        atomicAdd(&g_ssum[8 + g],  (double)(0.1f  * part[28]));
        atomicAdd(&g_ssq [8 + g],  (double)(0.01f * part[29]));
        atomicAdd(&g_ssum[16 + g], (double)(0.1f  * part[30]));
        atomicAdd(&g_ssq [16 + g], (double)(0.01f * part[31]));
    }
}

// ---- warp reduce-scatter: 16 partials spread over 8 consecutive lanes ------
// Input: av[16], v = 2*ch + r. Output: the 2 fully-reduced values (rows r=0,1)
// for channel ch = bitrev3(tj) held by this lane.
__device__ __forceinline__ void reduce_scatter16(const float* av, int tj,
                                                 float& o0, float& o1) {
    float a8[8];
#pragma unroll
    for (int v = 0; v < 8; ++v) {
        float snd = (tj & 1) ? av[v] : av[8 + v];
        float kp  = (tj & 1) ? av[8 + v] : av[v];
        a8[v] = kp + __shfl_xor_sync(0xffffffffu, snd, 1);
    }
    float a4[4];
#pragma unroll
    for (int v = 0; v < 4; ++v) {
        float snd = (tj & 2) ? a8[v] : a8[4 + v];
        float kp  = (tj & 2) ? a8[4 + v] : a8[v];
        a4[v] = kp + __shfl_xor_sync(0xffffffffu, snd, 2);
    }
    float a2[2];
#pragma unroll
    for (int v = 0; v < 2; ++v) {
        float snd = (tj & 4) ? a4[v] : a4[2 + v];
        float kp  = (tj & 4) ? a4[2 + v] : a4[v];
        a2[v] = kp + __shfl_xor_sync(0xffffffffu, snd, 4);
    }
    o0 = a2[0]; o1 = a2[1];
}

// ---------------- K3: attention — warp-shuffle reductions, 3 syncs ----------
// block = (b, g); 224 threads. warp w, lane l: tj = l&7, ig = l>>3,
// ti = w*4+ig (0..27), rows i0=2ti, i0+1; cols j0=7tj .. j0+6.
__global__ void __launch_bounds__(224, 5) k_attn(const float* __restrict__ relative,
                                                 const float* __restrict__ qg,
                                                 const float* __restrict__ qb,
                                                 const float* __restrict__ sg,
                                                 const float* __restrict__ sb) {
    __shared__ __align__(16) float qsT[56][4];
    __shared__ __align__(16) float ksT[56][4];
    __shared__ __align__(16) float vsT[56][8];
    __shared__ __align__(16) float relqT[111][4];
    __shared__ __align__(16) float relkT[111][4];
    __shared__ __align__(16) float relvT[111][12];
    __shared__ __align__(16) float SB[16][60];
    __shared__ float sQs[16], sQo[16], sC[4];

    const int b = blockIdx.x >> 3, g = blockIdx.x & 7;
    const int t = threadIdx.x;

    // folded finalizers
    if (t < 16) {
        int o = g * 16 + t;
        double inv = 1.0 / NQKV;
        double m = g_qsum[o] * inv;
        double v = g_qsq[o] * inv - m * m;
        float sc = qg[o] * rsqrtf((float)v + EPSBN);
        sQs[t] = sc;
        sQo[t] = qb[o] - (float)m * sc;
    }
    if (t == 16) {
        double inv = 1.0 / NSIM;
        float fac[3] = {1.f, 0.1f, 0.1f};
        float csum = 0.f;
        for (int r = 0; r < 3; ++r) {
            int idx = r * 8 + g;
            double m = g_ssum[idx] * inv;
            double v = g_ssq[idx] * inv - m * m;
            float aa = sg[idx] * rsqrtf((float)v + EPSBN);
            sC[r] = aa * fac[r];
            csum += sb[idx] - (float)m * aa;
        }
        sC[3] = csum;
    }
    __syncthreads();

    for (int idx = t; idx < 16 * 56; idx += 224) {
        int cc = idx / 56, i = idx % 56;
        float v = g_qkv[(size_t)b * CH_STR + (g * 16 + cc) * 56 + i] * sQs[cc] + sQo[cc];
        if (cc < 4) qsT[i][cc] = v;
        else if (cc < 8) ksT[i][cc - 4] = v;
        else vsT[i][cc - 8] = v;
    }
    for (int idx = t; idx < 16 * 111; idx += 224) {
        int c = idx / 111, d = idx % 111;
        float v = relative[idx];
        if (c < 4) relqT[d][c] = v;
        else if (c < 8) relkT[d][c - 4] = v;
        else relvT[d][c - 8] = v;
    }
    __syncthreads();

    const float cqk = sC[0], cqr = sC[1], ckr = sC[2], soff = sC[3];
    const int lane = t & 31;
    const int tj = lane & 7, ig = lane >> 3;
    const int ti = (t >> 5) * 4 + ig;
    const int i0 = ti * 2, j0 = tj * 7;
    const int dbase = i0 - j0 + 49;

    float4 q0v = *(const float4*)qsT[i0];
    float4 q1v = *(const float4*)qsT[i0 + 1];

    // ---- phase 1: logits by diagonals, rolling k ----
    float P[14];
    {
        float4 kcur, kprev;
#pragma unroll
        for (int cc = 0; cc < 8; ++cc) {
            int d = dbase + cc;
            float4 rq = *(const float4*)relqT[d];
            float4 rk = *(const float4*)relkT[110 - d];
            if (cc <= 6) {
                kcur = *(const float4*)ksT[j0 + 6 - cc];
                float qk = q0v.x * kcur.x + q0v.y * kcur.y + q0v.z * kcur.z + q0v.w * kcur.w;
                float qr = q0v.x * rq.x + q0v.y * rq.y + q0v.z * rq.z + q0v.w * rq.w;
                float kr = kcur.x * rk.x + kcur.y * rk.y + kcur.z * rk.z + kcur.w * rk.w;
                P[6 - cc] = fmaf(cqk, qk, fmaf(cqr, qr, fmaf(ckr, kr, soff)));
            }
            if (cc >= 1) {
                float qk = q1v.x * kprev.x + q1v.y * kprev.y + q1v.z * kprev.z + q1v.w * kprev.w;
                float qr = q1v.x * rq.x + q1v.y * rq.y + q1v.z * rq.z + q1v.w * rq.w;
                float kr = kprev.x * rk.x + kprev.y * rk.y + kprev.z * rk.z + kprev.w * rk.w;
                P[7 + 7 - cc] = fmaf(cqk, qk, fmaf(cqr, qr, fmaf(ckr, kr, soff)));
            }
            kprev = kcur;
        }
    }

    // ---- phase 2: exp + warp-butterfly row sums (no smem, no sync) ----
    float rinv0, rinv1;
    {
        float rs0 = 0.f, rs1 = 0.f;
#pragma unroll
        for (int jj = 0; jj < 7; ++jj) {
            float p0 = __expf(P[jj]);
            float p1 = __expf(P[7 + jj]);
            P[jj] = p0; P[7 + jj] = p1;
            rs0 += p0; rs1 += p1;
        }
#pragma unroll
        for (int m = 1; m < 8; m <<= 1) {
            rs0 += __shfl_xor_sync(0xffffffffu, rs0, m);
            rs1 += __shfl_xor_sync(0xffffffffu, rs1, m);
        }
        rinv0 = 1.0f / rs0;
        rinv1 = 1.0f / rs1;
    }

    const int chown = ((tj & 1) << 2) | (tj & 2) | ((tj >> 2) & 1);  // bitrev3(tj)

    // ---- phase 3a: sv partials + warp reduce-scatter ----
    {
        float av[16];
#pragma unroll
        for (int v = 0; v < 16; ++v) av[v] = 0.f;
#pragma unroll
        for (int jj = 0; jj < 7; ++jj) {
            float4 v0 = *(const float4*)&vsT[j0 + jj][0];
            float4 v1 = *(const float4*)&vsT[j0 + jj][4];
            float p0 = P[jj], p1 = P[7 + jj];
            av[0] += p0 * v0.x; av[1] += p1 * v0.x;
            av[2] += p0 * v0.y; av[3] += p1 * v0.y;
            av[4] += p0 * v0.z; av[5] += p1 * v0.z;
            av[6] += p0 * v0.w; av[7] += p1 * v0.w;
            av[8]  += p0 * v1.x; av[9]  += p1 * v1.x;
            av[10] += p0 * v1.y; av[11] += p1 * v1.y;
            av[12] += p0 * v1.z; av[13] += p1 * v1.z;
            av[14] += p0 * v1.w; av[15] += p1 * v1.w;
        }
        float s0, s1;
        reduce_scatter16(av, tj, s0, s1);
        SB[2 * chown][i0]     = s0 * rinv0;
        SB[2 * chown][i0 + 1] = s1 * rinv1;
    }

    // ---- phase 3b: sve partials (diagonal rel reuse) + reduce-scatter ----
    {
        float av[16];
#pragma unroll
        for (int v = 0; v < 16; ++v) av[v] = 0.f;
#pragma unroll
        for (int cc = 0; cc < 8; ++cc) {
            int d = dbase + cc;
            float4 r0 = *(const float4*)&relvT[d][0];
            float4 r1 = *(const float4*)&relvT[d][4];
            if (cc <= 6) {                     // row i0, jj = 6-cc
                float p = P[6 - cc];
                av[0] += p * r0.x; av[2] += p * r0.y; av[4]  += p * r0.z; av[6]  += p * r0.w;
                av[8] += p * r1.x; av[10] += p * r1.y; av[12] += p * r1.z; av[14] += p * r1.w;
            }
            if (cc >= 1) {                     // row i0+1, jj = 7-cc
                float p = P[7 + 7 - cc];
                av[1] += p * r0.x; av[3] += p * r0.y; av[5]  += p * r0.z; av[7]  += p * r0.w;
                av[9] += p * r1.x; av[11] += p * r1.y; av[13] += p * r1.z; av[15] += p * r1.w;
            }
        }
        float s0, s1;
        reduce_scatter16(av, tj, s0, s1);
        SB[2 * chown + 1][i0]     = s0 * rinv0 * 0.1f;
        SB[2 * chown + 1][i0 + 1] = s1 * rinv1 * 0.1f;
    }
    __syncthreads();

    // ---- coalesced float4 write to g_so ----
    {
        int row = t / 14, c4 = t % 14;         // 224 threads = 16 rows x 14 float4
        float4 v4 = *(const float4*)&SB[row][c4 * 4];
        float* ob = g_so + (size_t)b * CH_STR + g * 16 * 56;
        *(float4*)&ob[row * 56 + c4 * 4] = v4;
    }

    // ---- out stats: 128 threads = 16 rows x 8 lanes, butterfly reduce ----
    if (t < 128) {
        int row = t >> 3, sub = t & 7;
        float s1 = 0.f, s2 = 0.f;
#pragma unroll
        for (int e = 0; e < 7; ++e) {
            float v = SB[row][sub * 7 + e];
            s1 += v; s2 += v * v;
        }
#pragma unroll
        for (int m = 1; m < 8; m <<= 1) {
            s1 += __shfl_xor_sync(0xffffffffu, s1, m);
            s2 += __shfl_xor_sync(0xffffffffu, s2, m);
        }
        if (sub == 0) {
            atomicAdd(&g_osum[g * 16 + row], (double)s1);
            atomicAdd(&g_osq [g * 16 + row], (double)s2);
        }
    }
}

// ---------------- K4: out BN (folded finalize) + pair-sum + layout ----------
__global__ void __launch_bounds__(256) k_out(float* __restrict__ out,
                                             const float* __restrict__ og,
                                             const float* __restrict__ ob) {
    __shared__ float sOs[128], sOo[128];
    {
        int o = threadIdx.x;
        if (o < 128) {
            double inv = 1.0 / NQKV;
            double m = g_osum[o] * inv;
            double v = g_osq[o] * inv - m * m;
            float sc = og[o] * rsqrtf((float)v + EPSBN);
            sOs[o] = sc;
            sOo[o] = ob[o] - (float)m * sc;
        }
    }
    __syncthreads();
    int idx = blockIdx.x * 256 + threadIdx.x;
    if (idx >= 1605632) return;
    int e  = idx * 4;
    int cp = e / XPLANE;
    int r  = e % XPLANE;
    int bq = r / 56, i = r % 56;
    const float* base = g_so + (size_t)bq * CH_STR + (2 * cp) * 56 + i;
    float4 s0 = *(const float4*)base;
    float4 s1 = *(const float4*)(base + 56);
    float sc0 = sOs[2 * cp], of0 = sOo[2 * cp];
    float sc1 = sOs[2 * cp + 1], of1 = sOo[2 * cp + 1];
    float4 o4;
    o4.x = s0.x * sc0 + of0 + s1.x * sc1 + of1;
    o4.y = s0.y * sc0 + of0 + s1.y * sc1 + of1;
    o4.z = s0.z * sc0 + of0 + s1.z * sc1 + of1;
    o4.w = s0.w * sc0 + of0 + s1.w * sc1 + of1;
    *(float4*)&out[e] = o4;
}

// ---------------- launch -----------------------------------------------------
extern "C" void kernel_launch(void* const* d_in, const int* in_sizes, int n_in,
                              void* d_out, int out_size) {
    const float* x        = (const float*)d_in[0];
    const float* w_qkv    = (const float*)d_in[1];
    const float* relative = (const float*)d_in[2];
    const float* qg       = (const float*)d_in[3];
    const float* qb       = (const float*)d_in[4];
    const float* sg       = (const float*)d_in[5];
    const float* sb       = (const float*)d_in[6];
    const float* og       = (const float*)d_in[7];
    const float* ob       = (const float*)d_in[8];
    float* out            = (float*)d_out;

    k_init <<<1, 256>>>(relative);
    k_qkv  <<<BTOT, 256>>>(x, w_qkv);
    k_mom  <<<BTOT, 256>>>(qg, qb);
    k_attn <<<BTOT * 8, 224>>>(relative, qg, qb, sg, sb);
    k_out  <<<6272, 256>>>(out, og, ob);
}

// round 7
// speedup vs baseline: 1.1458x; 1.0142x over previous
#include <cuda_runtime.h>
#include <cuda_fp16.h>
#include <math.h>

// Problem constants
#define BTOT   1792          // N*D*H = 1*32*56
#define CH_STR 7168          // 128*56
#define XPLANE 100352        // 32*56*56 == BTOT*56
#define NQKV   100352.0
#define NSIM   5619712.0     // BTOT*56*56
#define EPSBN  1e-5f

// ---------------- scratch (device globals; no runtime alloc) ----------------
__device__ float g_qkv[BTOT * 128 * 56];   // [b][o][i]  o = g*16+cc (q:0-3,k:4-7,v:8-15)
__device__ float g_so [BTOT * 128 * 56];   // [b][o2][i]
__device__ double g_qsum[128], g_qsq[128];
__device__ double g_ssum[24],  g_ssq[24];
__device__ double g_osum[128], g_osq[128];
// precomputed relative-embedding moment tables
__device__ float g_SR[8][56];
__device__ float g_TQ[10][56];
__device__ float g_TK[10][56];

__constant__ int   c_PA[10] = {0,0,0,0,1,1,1,2,2,3};
__constant__ int   c_PB[10] = {0,1,2,3,1,2,3,2,3,3};
__constant__ float c_PW[10] = {1.f,2.f,2.f,2.f,1.f,2.f,2.f,1.f,2.f,1.f};

// ---------------- K_init: zero accumulators + prefix tables -----------------
__global__ void k_init(const float* __restrict__ relative) {
    __shared__ float rel[8][112];
    int t = threadIdx.x;
    if (t < 128) { g_qsum[t] = 0.0; g_qsq[t] = 0.0; g_osum[t] = 0.0; g_osq[t] = 0.0; }
    if (t < 24)  { g_ssum[t] = 0.0; g_ssq[t] = 0.0; }
    for (int idx = t; idx < 8 * 111; idx += 256)
        rel[idx / 111][idx % 111] = relative[idx];
    __syncthreads();
    for (int task = t; task < 448; task += 256) {
        int c = task / 56, i = task % 56;
        float s = 0.f;
        for (int d = 0; d < 56; ++d) s += rel[c][i + d];
        g_SR[c][i] = s;
    }
    for (int task = t; task < 1120; task += 256) {
        int p = task / 56, i = task % 56;
        int pp = p % 10; int isK = (p >= 10) ? 4 : 0;
        int a = c_PA[pp] + isK, bb = c_PB[pp] + isK;
        float s = 0.f;
        for (int d = 0; d < 56; ++d) s += rel[a][i + d] * rel[bb][i + d];
        s *= c_PW[pp];
        if (isK) g_TK[pp][i] = s; else g_TQ[pp][i] = s;
    }
}

// ---------------- K1: qkv = w @ x  (+ per-channel stats) --------------------
__global__ void __launch_bounds__(256) k_qkv(const float* __restrict__ x,
                                             const float* __restrict__ w) {
    __shared__ float xs[64][57];
    __shared__ float ws[128][65];
    const int b = blockIdx.x;
    for (int t = threadIdx.x; t < 64 * 56; t += 256) {
        int c = t / 56, i = t % 56;
        xs[c][i] = x[c * XPLANE + b * 56 + i];
    }
    for (int t = threadIdx.x; t < 128 * 64; t += 256)
        ws[t >> 6][t & 63] = w[t];
    __syncthreads();

    const int og = threadIdx.x >> 3;
    const int ig = threadIdx.x & 7;
    const int o0 = og * 4, i0 = ig * 7;
    float acc[4][7];
#pragma unroll
    for (int a = 0; a < 4; a++)
#pragma unroll
        for (int c2 = 0; c2 < 7; c2++) acc[a][c2] = 0.f;

    for (int c = 0; c < 64; ++c) {
        float w0 = ws[o0][c], w1 = ws[o0 + 1][c], w2 = ws[o0 + 2][c], w3 = ws[o0 + 3][c];
#pragma unroll
        for (int ii = 0; ii < 7; ++ii) {
            float xv = xs[c][i0 + ii];
            acc[0][ii] += w0 * xv; acc[1][ii] += w1 * xv;
            acc[2][ii] += w2 * xv; acc[3][ii] += w3 * xv;
        }
    }
    float* outb = g_qkv + (size_t)b * CH_STR;
#pragma unroll
    for (int oo = 0; oo < 4; ++oo) {
        float s = 0.f, sq = 0.f;
#pragma unroll
        for (int ii = 0; ii < 7; ++ii) {
            float v = acc[oo][ii];
            outb[(o0 + oo) * 56 + i0 + ii] = v;
            s += v; sq += v * v;
        }
        for (int off = 4; off; off >>= 1) {
            s  += __shfl_down_sync(0xffffffffu, s,  off);
            sq += __shfl_down_sync(0xffffffffu, sq, off);
        }
        if (ig == 0) {
            atomicAdd(&g_qsum[o0 + oo], (double)s);
            atomicAdd(&g_qsq [o0 + oo], (double)sq);
        }
    }
}

// ---------------- K2: analytic sim moments (folds qkv-BN finalize) ----------
__global__ void __launch_bounds__(256) k_mom(const float* __restrict__ qg,
                                             const float* __restrict__ qb) {
    __shared__ float sQs[128], sQo[128];
    const int b = blockIdx.x;
    {
        int o = threadIdx.x;
        if (o < 128) {
            double inv = 1.0 / NQKV;
            double m = g_qsum[o] * inv;
            double v = g_qsq[o] * inv - m * m;
            float sc = qg[o] * rsqrtf((float)v + EPSBN);
            sQs[o] = sc;
            sQo[o] = qb[o] - (float)m * sc;
        }
    }
    __syncthreads();

    const int g = threadIdx.x >> 5;
    const int lane = threadIdx.x & 31;
    const float* base = g_qkv + (size_t)b * CH_STR + g * 16 * 56;

    float part[32];
#pragma unroll
    for (int v = 0; v < 32; ++v) part[v] = 0.f;

#pragma unroll
    for (int ii = 0; ii < 2; ++ii) {
        int i = lane + ii * 32;
        if (i < 56) {
            float q[4], k[4];
#pragma unroll
            for (int c = 0; c < 4; ++c) {
                int oq = g * 16 + c, ok = g * 16 + 4 + c;
                q[c] = base[c * 56 + i]       * sQs[oq] + sQo[oq];
                k[c] = base[(4 + c) * 56 + i] * sQs[ok] + sQo[ok];
            }
#pragma unroll
            for (int c = 0; c < 4; ++c) {
                part[c]     += q[c];
                part[4 + c] += k[c];
                part[28] += q[c] * g_SR[c][i];
                part[30] += k[c] * g_SR[4 + c][i];
            }
#pragma unroll
            for (int p = 0; p < 10; ++p) {
                float pq = q[c_PA[p]] * q[c_PB[p]];
                float pk = k[c_PA[p]] * k[c_PB[p]];
                part[8 + p]  += pq;
                part[18 + p] += pk;
                part[29] += pq * g_TQ[p][i];
                part[31] += pk * g_TK[p][i];
            }
        }
    }
#pragma unroll
    for (int v = 0; v < 32; ++v)
        for (int off = 16; off; off >>= 1)
            part[v] += __shfl_down_sync(0xffffffffu, part[v], off);

    if (lane == 0) {
        float S1 = 0.f, S2 = 0.f;
#pragma unroll
        for (int c = 0; c < 4; ++c) S1 += part[c] * part[4 + c];
#pragma unroll
        for (int p = 0; p < 10; ++p) S2 += c_PW[p] * part[8 + p] * part[18 + p];
        atomicAdd(&g_ssum[g],      (double)S1);
        atomicAdd(&g_ssq [g],      (double)S2);
        atomicAdd(&g_ssum[8 + g],  (double)(0.1f  * part[28]));
        atomicAdd(&g_ssq [8 + g],  (double)(0.01f * part[29]));
        atomicAdd(&g_ssum[16 + g], (double)(0.1f  * part[30]));
        atomicAdd(&g_ssq [16 + g], (double)(0.01f * part[31]));
    }
}

// ---- warp reduce-scatter: 16 partials spread over 8 consecutive lanes ------
__device__ __forceinline__ void reduce_scatter16(const float* av, int tj,
                                                 float& o0, float& o1) {
    float a8[8];
#pragma unroll
    for (int v = 0; v < 8; ++v) {
        float snd = (tj & 1) ? av[v] : av[8 + v];
        float kp  = (tj & 1) ? av[8 + v] : av[v];
        a8[v] = kp + __shfl_xor_sync(0xffffffffu, snd, 1);
    }
    float a4[4];
#pragma unroll
    for (int v = 0; v < 4; ++v) {
        float snd = (tj & 2) ? a8[v] : a8[4 + v];
        float kp  = (tj & 2) ? a8[4 + v] : a8[v];
        a4[v] = kp + __shfl_xor_sync(0xffffffffu, snd, 2);
    }
    float a2[2];
#pragma unroll
    for (int v = 0; v < 2; ++v) {
        float snd = (tj & 4) ? a4[v] : a4[2 + v];
        float kp  = (tj & 4) ? a4[2 + v] : a4[v];
        a2[v] = kp + __shfl_xor_sync(0xffffffffu, snd, 4);
    }
    o0 = a2[0]; o1 = a2[1];
}

// ---------------- K3: attention — fp16-packed rel tables --------------------
// block = (b, g); 224 threads. warp w, lane l: tj = l&7, ig = l>>3,
// ti = w*4+ig (0..27), rows i0=2ti, i0+1; cols j0=7tj .. j0+6.
__global__ void __launch_bounds__(224, 5) k_attn(const float* __restrict__ relative,
                                                 const float* __restrict__ qg,
                                                 const float* __restrict__ qb,
                                                 const float* __restrict__ sg,
                                                 const float* __restrict__ sb) {
    __shared__ __align__(16) float qsT[56][4];
    __shared__ __align__(16) float ksT[56][4];
    __shared__ __align__(16) float vsT[56][8];
    // relQK[d] = { relq[0..3][d] , relk[0..3][110-d] }  (8 halves = 16B row)
    __shared__ __align__(16) __half relQK[111][8];
    // relV[d]  = { relv[0..7][d] }                      (8 halves = 16B row)
    __shared__ __align__(16) __half relV[111][8];
    __shared__ __align__(16) float SB[16][60];
    __shared__ float sQs[16], sQo[16], sC[4];

    const int b = blockIdx.x >> 3, g = blockIdx.x & 7;
    const int t = threadIdx.x;

    // folded finalizers
    if (t < 16) {
        int o = g * 16 + t;
        double inv = 1.0 / NQKV;
        double m = g_qsum[o] * inv;
        double v = g_qsq[o] * inv - m * m;
        float sc = qg[o] * rsqrtf((float)v + EPSBN);
        sQs[t] = sc;
        sQo[t] = qb[o] - (float)m * sc;
    }
    if (t == 16) {
        double inv = 1.0 / NSIM;
        float fac[3] = {1.f, 0.1f, 0.1f};
        float csum = 0.f;
        for (int r = 0; r < 3; ++r) {
            int idx = r * 8 + g;
            double m = g_ssum[idx] * inv;
            double v = g_ssq[idx] * inv - m * m;
            float aa = sg[idx] * rsqrtf((float)v + EPSBN);
            sC[r] = aa * fac[r];
            csum += sb[idx] - (float)m * aa;
        }
        sC[3] = csum;
    }
    __syncthreads();

    for (int idx = t; idx < 16 * 56; idx += 224) {
        int cc = idx / 56, i = idx % 56;
        float v = g_qkv[(size_t)b * CH_STR + (g * 16 + cc) * 56 + i] * sQs[cc] + sQo[cc];
        if (cc < 4) qsT[i][cc] = v;
        else if (cc < 8) ksT[i][cc - 4] = v;
        else vsT[i][cc - 8] = v;
    }
    for (int idx = t; idx < 8 * 111; idx += 224) {
        int c = idx / 111, d = idx % 111;
        if (c < 4) relQK[d][c] = __float2half(relative[c * 111 + d]);
        else       relQK[d][c] = __float2half(relative[c * 111 + (110 - d)]); // relk at 110-d
    }
    for (int idx = t; idx < 8 * 111; idx += 224) {
        int c = idx / 111, d = idx % 111;
        relV[d][c] = __float2half(relative[(8 + c) * 111 + d]);
    }
    __syncthreads();

    const float cqk = sC[0], cqr = sC[1], ckr = sC[2], soff = sC[3];
    const int lane = t & 31;
    const int tj = lane & 7, ig = lane >> 3;
    const int ti = (t >> 5) * 4 + ig;
    const int i0 = ti * 2, j0 = tj * 7;
    const int dbase = i0 - j0 + 49;

    float4 q0v = *(const float4*)qsT[i0];
    float4 q1v = *(const float4*)qsT[i0 + 1];

    // ---- phase 1: logits by diagonals, rolling k, fused fp16 rel row ----
    float P[14];
    {
        float4 kcur, kprev;
#pragma unroll
        for (int cc = 0; cc < 8; ++cc) {
            int d = dbase + cc;
            uint4 rw = *(const uint4*)relQK[d];
            const __half2* hp = (const __half2*)&rw;
            float2 ra = __half22float2(hp[0]);   // relq ch0,1 @ d
            float2 rb = __half22float2(hp[1]);   // relq ch2,3 @ d
            float2 rc = __half22float2(hp[2]);   // relk ch0,1 @ 110-d
            float2 rd = __half22float2(hp[3]);   // relk ch2,3 @ 110-d
            if (cc <= 6) {
                kcur = *(const float4*)ksT[j0 + 6 - cc];
                float qk = q0v.x * kcur.x + q0v.y * kcur.y + q0v.z * kcur.z + q0v.w * kcur.w;
                float qr = q0v.x * ra.x + q0v.y * ra.y + q0v.z * rb.x + q0v.w * rb.y;
                float kr = kcur.x * rc.x + kcur.y * rc.y + kcur.z * rd.x + kcur.w * rd.y;
                P[6 - cc] = fmaf(cqk, qk, fmaf(cqr, qr, fmaf(ckr, kr, soff)));
            }
            if (cc >= 1) {
                float qk = q1v.x * kprev.x + q1v.y * kprev.y + q1v.z * kprev.z + q1v.w * kprev.w;
                float qr = q1v.x * ra.x + q1v.y * ra.y + q1v.z * rb.x + q1v.w * rb.y;
                float kr = kprev.x * rc.x + kprev.y * rc.y + kprev.z * rd.x + kprev.w * rd.y;
                P[7 + 7 - cc] = fmaf(cqk, qk, fmaf(cqr, qr, fmaf(ckr, kr, soff)));
            }
            kprev = kcur;
        }
    }

    // ---- phase 2: exp + warp-butterfly row sums ----
    float rinv0, rinv1;
    {
        float rs0 = 0.f, rs1 = 0.f;
#pragma unroll
        for (int jj = 0; jj < 7; ++jj) {
            float p0 = __expf(P[jj]);
            float p1 = __expf(P[7 + jj]);
            P[jj] = p0; P[7 + jj] = p1;
            rs0 += p0; rs1 += p1;
        }
#pragma unroll
        for (int m = 1; m < 8; m <<= 1) {
            rs0 += __shfl_xor_sync(0xffffffffu, rs0, m);
            rs1 += __shfl_xor_sync(0xffffffffu, rs1, m);
        }
        rinv0 = 1.0f / rs0;
        rinv1 = 1.0f / rs1;
    }

    const int chown = ((tj & 1) << 2) | (tj & 2) | ((tj >> 2) & 1);  // bitrev3(tj)

    // ---- phase 3a: sv partials + warp reduce-scatter ----
    {
        float av[16];
#pragma unroll
        for (int v = 0; v < 16; ++v) av[v] = 0.f;
#pragma unroll
        for (int jj = 0; jj < 7; ++jj) {
            float4 v0 = *(const float4*)&vsT[j0 + jj][0];
            float4 v1 = *(const float4*)&vsT[j0 + jj][4];
            float p0 = P[jj], p1 = P[7 + jj];
            av[0] += p0 * v0.x; av[1] += p1 * v0.x;
            av[2] += p0 * v0.y; av[3] += p1 * v0.y;
            av[4] += p0 * v0.z; av[5] += p1 * v0.z;
            av[6] += p0 * v0.w; av[7] += p1 * v0.w;
            av[8]  += p0 * v1.x; av[9]  += p1 * v1.x;
            av[10] += p0 * v1.y; av[11] += p1 * v1.y;
            av[12] += p0 * v1.z; av[13] += p1 * v1.z;
            av[14] += p0 * v1.w; av[15] += p1 * v1.w;
        }
        float s0, s1;
        reduce_scatter16(av, tj, s0, s1);
        SB[2 * chown][i0]     = s0 * rinv0;
        SB[2 * chown][i0 + 1] = s1 * rinv1;
    }

    // ---- phase 3b: sve partials (fp16 relv rows) + reduce-scatter ----
    {
        float av[16];
#pragma unroll
        for (int v = 0; v < 16; ++v) av[v] = 0.f;
#pragma unroll
        for (int cc = 0; cc < 8; ++cc) {
            int d = dbase + cc;
            uint4 rw = *(const uint4*)relV[d];
            const __half2* hp = (const __half2*)&rw;
            float2 va = __half22float2(hp[0]);  // ch0,1
            float2 vb = __half22float2(hp[1]);  // ch2,3
            float2 vc = __half22float2(hp[2]);  // ch4,5
            float2 vd = __half22float2(hp[3]);  // ch6,7
            if (cc <= 6) {                     // row i0, jj = 6-cc
                float p = P[6 - cc];
                av[0] += p * va.x; av[2]  += p * va.y; av[4]  += p * vb.x; av[6]  += p * vb.y;
                av[8] += p * vc.x; av[10] += p * vc.y; av[12] += p * vd.x; av[14] += p * vd.y;
            }
            if (cc >= 1) {                     // row i0+1, jj = 7-cc
                float p = P[7 + 7 - cc];
                av[1] += p * va.x; av[3]  += p * va.y; av[5]  += p * vb.x; av[7]  += p * vb.y;
                av[9] += p * vc.x; av[11] += p * vc.y; av[13] += p * vd.x; av[15] += p * vd.y;
            }
        }
        float s0, s1;
        reduce_scatter16(av, tj, s0, s1);
        SB[2 * chown + 1][i0]     = s0 * rinv0 * 0.1f;
        SB[2 * chown + 1][i0 + 1] = s1 * rinv1 * 0.1f;
    }
    __syncthreads();

    // ---- coalesced float4 write to g_so ----
    {
        int row = t / 14, c4 = t % 14;         // 224 threads = 16 rows x 14 float4
        float4 v4 = *(const float4*)&SB[row][c4 * 4];
        float* ob = g_so + (size_t)b * CH_STR + g * 16 * 56;
        *(float4*)&ob[row * 56 + c4 * 4] = v4;
    }

    // ---- out stats: 128 threads = 16 rows x 8 lanes, butterfly reduce ----
    if (t < 128) {
        int row = t >> 3, sub = t & 7;
        float s1 = 0.f, s2 = 0.f;
#pragma unroll
        for (int e = 0; e < 7; ++e) {
            float v = SB[row][sub * 7 + e];
            s1 += v; s2 += v * v;
        }
#pragma unroll
        for (int m = 1; m < 8; m <<= 1) {
            s1 += __shfl_xor_sync(0xffffffffu, s1, m);
            s2 += __shfl_xor_sync(0xffffffffu, s2, m);
        }
        if (sub == 0) {
            atomicAdd(&g_osum[g * 16 + row], (double)s1);
            atomicAdd(&g_osq [g * 16 + row], (double)s2);
        }
    }
}

// ---------------- K4: out BN (folded finalize) + pair-sum + layout ----------
__global__ void __launch_bounds__(256) k_out(float* __restrict__ out,
                                             const float* __restrict__ og,
                                             const float* __restrict__ ob) {
    __shared__ float sOs[128], sOo[128];
    {
        int o = threadIdx.x;
        if (o < 128) {
            double inv = 1.0 / NQKV;
            double m = g_osum[o] * inv;
            double v = g_osq[o] * inv - m * m;
            float sc = og[o] * rsqrtf((float)v + EPSBN);
            sOs[o] = sc;
            sOo[o] = ob[o] - (float)m * sc;
        }
    }
    __syncthreads();
    int idx = blockIdx.x * 256 + threadIdx.x;
    if (idx >= 1605632) return;
    int e  = idx * 4;
    int cp = e / XPLANE;
    int r  = e % XPLANE;
    int bq = r / 56, i = r % 56;
    const float* base = g_so + (size_t)bq * CH_STR + (2 * cp) * 56 + i;
    float4 s0 = *(const float4*)base;
    float4 s1 = *(const float4*)(base + 56);
    float sc0 = sOs[2 * cp], of0 = sOo[2 * cp];
    float sc1 = sOs[2 * cp + 1], of1 = sOo[2 * cp + 1];
    float4 o4;
    o4.x = s0.x * sc0 + of0 + s1.x * sc1 + of1;
    o4.y = s0.y * sc0 + of0 + s1.y * sc1 + of1;
    o4.z = s0.z * sc0 + of0 + s1.z * sc1 + of1;
    o4.w = s0.w * sc0 + of0 + s1.w * sc1 + of1;
    *(float4*)&out[e] = o4;
}

// ---------------- launch -----------------------------------------------------
extern "C" void kernel_launch(void* const* d_in, const int* in_sizes, int n_in,
                              void* d_out, int out_size) {
    const float* x        = (const float*)d_in[0];
    const float* w_qkv    = (const float*)d_in[1];
    const float* relative = (const float*)d_in[2];
    const float* qg       = (const float*)d_in[3];
    const float* qb       = (const float*)d_in[4];
    const float* sg       = (const float*)d_in[5];
    const float* sb       = (const float*)d_in[6];
    const float* og       = (const float*)d_in[7];
    const float* ob       = (const float*)d_in[8];
    float* out            = (float*)d_out;

    k_init <<<1, 256>>>(relative);
    k_qkv  <<<BTOT, 256>>>(x, w_qkv);
    k_mom  <<<BTOT, 256>>>(qg, qb);
    k_attn <<<BTOT * 8, 224>>>(relative, qg, qb, sg, sb);
    k_out  <<<6272, 256>>>(out, og, ob);
}

// round 8
// speedup vs baseline: 1.2606x; 1.1002x over previous
#include <cuda_runtime.h>
#include <cuda_fp16.h>
#include <math.h>

// Problem constants
#define BTOT   1792          // N*D*H = 1*32*56
#define CH_STR 7168          // 128*56
#define XPLANE 100352        // 32*56*56 == BTOT*56
#define NQKV   100352.0
#define NSIM   5619712.0     // BTOT*56*56
#define EPSBN  1e-5f

// ---------------- scratch (device globals; no runtime alloc) ----------------
__device__ float g_qkv[BTOT * 128 * 56];   // [b][o][i]  o = g*16+cc (q:0-3,k:4-7,v:8-15)
__device__ float g_so [BTOT * 128 * 56];   // [b][o2][i]
__device__ double g_qsum[128], g_qsq[128];
__device__ double g_ssum[24],  g_ssq[24];
__device__ double g_osum[128], g_osq[128];
// precomputed relative-embedding moment tables
__device__ float g_SR[8][56];
__device__ float g_TQ[10][56];
__device__ float g_TK[10][56];

__constant__ int   c_PA[10] = {0,0,0,0,1,1,1,2,2,3};
__constant__ int   c_PB[10] = {0,1,2,3,1,2,3,2,3,3};
__constant__ float c_PW[10] = {1.f,2.f,2.f,2.f,1.f,2.f,2.f,1.f,2.f,1.f};

// ---------------- K_init: zero accumulators + prefix tables -----------------
__global__ void k_init(const float* __restrict__ relative) {
    __shared__ float rel[8][112];
    int t = threadIdx.x;
    if (t < 128) { g_qsum[t] = 0.0; g_qsq[t] = 0.0; g_osum[t] = 0.0; g_osq[t] = 0.0; }
    if (t < 24)  { g_ssum[t] = 0.0; g_ssq[t] = 0.0; }
    for (int idx = t; idx < 8 * 111; idx += 256)
        rel[idx / 111][idx % 111] = relative[idx];
    __syncthreads();
    for (int task = t; task < 448; task += 256) {
        int c = task / 56, i = task % 56;
        float s = 0.f;
        for (int d = 0; d < 56; ++d) s += rel[c][i + d];
        g_SR[c][i] = s;
    }
    for (int task = t; task < 1120; task += 256) {
        int p = task / 56, i = task % 56;
        int pp = p % 10; int isK = (p >= 10) ? 4 : 0;
        int a = c_PA[pp] + isK, bb = c_PB[pp] + isK;
        float s = 0.f;
        for (int d = 0; d < 56; ++d) s += rel[a][i + d] * rel[bb][i + d];
        s *= c_PW[pp];
        if (isK) g_TK[pp][i] = s; else g_TQ[pp][i] = s;
    }
}

// ---------------- K1: qkv = w @ x  (+ per-channel stats) --------------------
__global__ void __launch_bounds__(256) k_qkv(const float* __restrict__ x,
                                             const float* __restrict__ w) {
    __shared__ float xs[64][57];
    __shared__ float ws[128][65];
    const int b = blockIdx.x;
    for (int t = threadIdx.x; t < 64 * 56; t += 256) {
        int c = t / 56, i = t % 56;
        xs[c][i] = x[c * XPLANE + b * 56 + i];
    }
    for (int t = threadIdx.x; t < 128 * 64; t += 256)
        ws[t >> 6][t & 63] = w[t];
    __syncthreads();

    const int og = threadIdx.x >> 3;
    const int ig = threadIdx.x & 7;
    const int o0 = og * 4, i0 = ig * 7;
    float acc[4][7];
#pragma unroll
    for (int a = 0; a < 4; a++)
#pragma unroll
        for (int c2 = 0; c2 < 7; c2++) acc[a][c2] = 0.f;

    for (int c = 0; c < 64; ++c) {
        float w0 = ws[o0][c], w1 = ws[o0 + 1][c], w2 = ws[o0 + 2][c], w3 = ws[o0 + 3][c];
#pragma unroll
        for (int ii = 0; ii < 7; ++ii) {
            float xv = xs[c][i0 + ii];
            acc[0][ii] += w0 * xv; acc[1][ii] += w1 * xv;
            acc[2][ii] += w2 * xv; acc[3][ii] += w3 * xv;
        }
    }
    float* outb = g_qkv + (size_t)b * CH_STR;
#pragma unroll
    for (int oo = 0; oo < 4; ++oo) {
        float s = 0.f, sq = 0.f;
#pragma unroll
        for (int ii = 0; ii < 7; ++ii) {
            float v = acc[oo][ii];
            outb[(o0 + oo) * 56 + i0 + ii] = v;
            s += v; sq += v * v;
        }
        for (int off = 4; off; off >>= 1) {
            s  += __shfl_down_sync(0xffffffffu, s,  off);
            sq += __shfl_down_sync(0xffffffffu, sq, off);
        }
        if (ig == 0) {
            atomicAdd(&g_qsum[o0 + oo], (double)s);
            atomicAdd(&g_qsq [o0 + oo], (double)sq);
        }
    }
}

// ---------------- K2: analytic sim moments (folds qkv-BN finalize) ----------
__global__ void __launch_bounds__(256) k_mom(const float* __restrict__ qg,
                                             const float* __restrict__ qb) {
    __shared__ float sQs[128], sQo[128];
    const int b = blockIdx.x;
    {
        int o = threadIdx.x;
        if (o < 128) {
            double inv = 1.0 / NQKV;
            double m = g_qsum[o] * inv;
            double v = g_qsq[o] * inv - m * m;
            float sc = qg[o] * rsqrtf((float)v + EPSBN);
            sQs[o] = sc;
            sQo[o] = qb[o] - (float)m * sc;
        }
    }
    __syncthreads();

    const int g = threadIdx.x >> 5;
    const int lane = threadIdx.x & 31;
    const float* base = g_qkv + (size_t)b * CH_STR + g * 16 * 56;

    float part[32];
#pragma unroll
    for (int v = 0; v < 32; ++v) part[v] = 0.f;

#pragma unroll
    for (int ii = 0; ii < 2; ++ii) {
        int i = lane + ii * 32;
        if (i < 56) {
            float q[4], k[4];
#pragma unroll
            for (int c = 0; c < 4; ++c) {
                int oq = g * 16 + c, ok = g * 16 + 4 + c;
                q[c] = base[c * 56 + i]       * sQs[oq] + sQo[oq];
                k[c] = base[(4 + c) * 56 + i] * sQs[ok] + sQo[ok];
            }
#pragma unroll
            for (int c = 0; c < 4; ++c) {
                part[c]     += q[c];
                part[4 + c] += k[c];
                part[28] += q[c] * g_SR[c][i];
                part[30] += k[c] * g_SR[4 + c][i];
            }
#pragma unroll
            for (int p = 0; p < 10; ++p) {
                float pq = q[c_PA[p]] * q[c_PB[p]];
                float pk = k[c_PA[p]] * k[c_PB[p]];
                part[8 + p]  += pq;
                part[18 + p] += pk;
                part[29] += pq * g_TQ[p][i];
                part[31] += pk * g_TK[p][i];
            }
        }
    }
#pragma unroll
    for (int v = 0; v < 32; ++v)
        for (int off = 16; off; off >>= 1)
            part[v] += __shfl_down_sync(0xffffffffu, part[v], off);

    if (lane == 0) {
        float S1 = 0.f, S2 = 0.f;
#pragma unroll
        for (int c = 0; c < 4; ++c) S1 += part[c] * part[4 + c];
#pragma unroll
        for (int p = 0; p < 10; ++p) S2 += c_PW[p] * part[8 + p] * part[18 + p];
        atomicAdd(&g_ssum[g],      (double)S1);
        atomicAdd(&g_ssq [g],      (double)S2);
        atomicAdd(&g_ssum[8 + g],  (double)(0.1f  * part[28]));
        atomicAdd(&g_ssq [8 + g],  (double)(0.01f * part[29]));
        atomicAdd(&g_ssum[16 + g], (double)(0.1f  * part[30]));
        atomicAdd(&g_ssq [16 + g], (double)(0.01f * part[31]));
    }
}

// ---- warp reduce-scatter: 16 partials spread over 8 consecutive lanes ------
__device__ __forceinline__ void reduce_scatter16(const float* av, int tj,
                                                 float& o0, float& o1) {
    float a8[8];
#pragma unroll
    for (int v = 0; v < 8; ++v) {
        float snd = (tj & 1) ? av[v] : av[8 + v];
        float kp  = (tj & 1) ? av[8 + v] : av[v];
        a8[v] = kp + __shfl_xor_sync(0xffffffffu, snd, 1);
    }
    float a4[4];
#pragma unroll
    for (int v = 0; v < 4; ++v) {
        float snd = (tj & 2) ? a8[v] : a8[4 + v];
        float kp  = (tj & 2) ? a8[4 + v] : a8[v];
        a4[v] = kp + __shfl_xor_sync(0xffffffffu, snd, 2);
    }
    float a2[2];
#pragma unroll
    for (int v = 0; v < 2; ++v) {
        float snd = (tj & 4) ? a4[v] : a4[2 + v];
        float kp  = (tj & 4) ? a4[2 + v] : a4[v];
        a2[v] = kp + __shfl_xor_sync(0xffffffffu, snd, 4);
    }
    o0 = a2[0]; o1 = a2[1];
}

// ---------------- K3: attention — block = b, loop over 8 heads --------------
// 224 threads. warp w, lane l: tj = l&7, ig = l>>3, ti = w*4+ig (0..27),
// rows i0=2ti, i0+1; cols j0=7tj..7tj+6. Rel tables loaded ONCE per block.
__global__ void __launch_bounds__(224, 5) k_attn(const float* __restrict__ relative,
                                                 const float* __restrict__ qg,
                                                 const float* __restrict__ qb,
                                                 const float* __restrict__ sg,
                                                 const float* __restrict__ sb) {
    __shared__ __align__(16) float qsT[8][56][4];
    __shared__ __align__(16) float ksT[8][56][4];
    __shared__ __align__(16) float vsT[8][56][8];
    // relQK[d] = { relq[0..3][d] , relk[0..3][110-d] }  (8 halves = 16B row)
    __shared__ __align__(16) __half relQK[111][8];
    // relV[d]  = { relv[0..7][d] }                      (8 halves = 16B row)
    __shared__ __align__(16) __half relV[111][8];
    __shared__ __align__(16) float SB[16][60];
    __shared__ float sQs[128], sQo[128], sC[32];

    const int b = blockIdx.x;
    const int t = threadIdx.x;

    // ---- folded finalizers: all 128 qkv-BN channels + 8 heads' sim coeffs --
    if (t < 128) {
        double inv = 1.0 / NQKV;
        double m = g_qsum[t] * inv;
        double v = g_qsq[t] * inv - m * m;
        float sc = qg[t] * rsqrtf((float)v + EPSBN);
        sQs[t] = sc;
        sQo[t] = qb[t] - (float)m * sc;
    } else if (t < 136) {
        int g = t - 128;
        double inv = 1.0 / NSIM;
        float fac[3] = {1.f, 0.1f, 0.1f};
        float csum = 0.f;
        for (int r = 0; r < 3; ++r) {
            int idx = r * 8 + g;
            double m = g_ssum[idx] * inv;
            double v = g_ssq[idx] * inv - m * m;
            float aa = sg[idx] * rsqrtf((float)v + EPSBN);
            sC[4 * g + r] = aa * fac[r];
            csum += sb[idx] - (float)m * aa;
        }
        sC[4 * g + 3] = csum;
    }
    // ---- rel tables (once per block) ----
    for (int idx = t; idx < 8 * 111; idx += 224) {
        int c = idx / 111, d = idx % 111;
        if (c < 4) relQK[d][c] = __float2half(relative[c * 111 + d]);
        else       relQK[d][c] = __float2half(relative[c * 111 + (110 - d)]);
    }
    for (int idx = t; idx < 8 * 111; idx += 224) {
        int c = idx / 111, d = idx % 111;
        relV[d][c] = __float2half(relative[(8 + c) * 111 + d]);
    }
    __syncthreads();

    // ---- stage all 128 BN'd channels via float4 loads ----
    {
        const float* src = g_qkv + (size_t)b * CH_STR;
        const int chr = t / 14, i4 = t % 14;   // 16 channels x 14 float4 per iter
#pragma unroll
        for (int it = 0; it < 8; ++it) {
            int ch = it * 16 + chr;
            float4 v = *(const float4*)&src[ch * 56 + i4 * 4];
            float sc = sQs[ch], of = sQo[ch];
            float vals[4] = {v.x * sc + of, v.y * sc + of, v.z * sc + of, v.w * sc + of};
            int g = ch >> 4, cc = ch & 15;
#pragma unroll
            for (int e = 0; e < 4; ++e) {
                int i = i4 * 4 + e;
                if (cc < 4) qsT[g][i][cc] = vals[e];
                else if (cc < 8) ksT[g][i][cc - 4] = vals[e];
                else vsT[g][i][cc - 8] = vals[e];
            }
        }
    }
    __syncthreads();

    const int lane = t & 31;
    const int tj = lane & 7, ig = lane >> 3;
    const int ti = (t >> 5) * 4 + ig;
    const int i0 = ti * 2, j0 = tj * 7;
    const int dbase = i0 - j0 + 49;
    const int chown = ((tj & 1) << 2) | (tj & 2) | ((tj >> 2) & 1);  // bitrev3(tj)
    const int row_w = t / 14, c4_w = t % 14;   // g_so write mapping

#pragma unroll 1
    for (int g = 0; g < 8; ++g) {
        const float cqk = sC[4 * g], cqr = sC[4 * g + 1], ckr = sC[4 * g + 2], soff = sC[4 * g + 3];

        float4 q0v = *(const float4*)qsT[g][i0];
        float4 q1v = *(const float4*)qsT[g][i0 + 1];

        // ---- phase 1: logits by diagonals, rolling k, fused fp16 rel row ----
        float P[14];
        {
            float4 kcur, kprev;
#pragma unroll
            for (int cc = 0; cc < 8; ++cc) {
                int d = dbase + cc;
                uint4 rw = *(const uint4*)relQK[d];
                const __half2* hp = (const __half2*)&rw;
                float2 ra = __half22float2(hp[0]);
                float2 rb = __half22float2(hp[1]);
                float2 rc = __half22float2(hp[2]);
                float2 rd = __half22float2(hp[3]);
                if (cc <= 6) {
                    kcur = *(const float4*)ksT[g][j0 + 6 - cc];
                    float qk = q0v.x * kcur.x + q0v.y * kcur.y + q0v.z * kcur.z + q0v.w * kcur.w;
                    float qr = q0v.x * ra.x + q0v.y * ra.y + q0v.z * rb.x + q0v.w * rb.y;
                    float kr = kcur.x * rc.x + kcur.y * rc.y + kcur.z * rd.x + kcur.w * rd.y;
                    P[6 - cc] = fmaf(cqk, qk, fmaf(cqr, qr, fmaf(ckr, kr, soff)));
                }
                if (cc >= 1) {
                    float qk = q1v.x * kprev.x + q1v.y * kprev.y + q1v.z * kprev.z + q1v.w * kprev.w;
                    float qr = q1v.x * ra.x + q1v.y * ra.y + q1v.z * rb.x + q1v.w * rb.y;
                    float kr = kprev.x * rc.x + kprev.y * rc.y + kprev.z * rd.x + kprev.w * rd.y;
                    P[7 + 7 - cc] = fmaf(cqk, qk, fmaf(cqr, qr, fmaf(ckr, kr, soff)));
                }
                kprev = kcur;
            }
        }

        // ---- phase 2: exp + warp-butterfly row sums ----
        float rinv0, rinv1;
        {
            float rs0 = 0.f, rs1 = 0.f;
#pragma unroll
            for (int jj = 0; jj < 7; ++jj) {
                float p0 = __expf(P[jj]);
                float p1 = __expf(P[7 + jj]);
                P[jj] = p0; P[7 + jj] = p1;
                rs0 += p0; rs1 += p1;
            }
#pragma unroll
            for (int m = 1; m < 8; m <<= 1) {
                rs0 += __shfl_xor_sync(0xffffffffu, rs0, m);
                rs1 += __shfl_xor_sync(0xffffffffu, rs1, m);
            }
            rinv0 = 1.0f / rs0;
            rinv1 = 1.0f / rs1;
        }

        // ---- phase 3a: sv partials + warp reduce-scatter ----
        {
            float av[16];
#pragma unroll
            for (int v = 0; v < 16; ++v) av[v] = 0.f;
#pragma unroll
            for (int jj = 0; jj < 7; ++jj) {
                float4 v0 = *(const float4*)&vsT[g][j0 + jj][0];
                float4 v1 = *(const float4*)&vsT[g][j0 + jj][4];
                float p0 = P[jj], p1 = P[7 + jj];
                av[0] += p0 * v0.x; av[1] += p1 * v0.x;
                av[2] += p0 * v0.y; av[3] += p1 * v0.y;
                av[4] += p0 * v0.z; av[5] += p1 * v0.z;
                av[6] += p0 * v0.w; av[7] += p1 * v0.w;
                av[8]  += p0 * v1.x; av[9]  += p1 * v1.x;
                av[10] += p0 * v1.y; av[11] += p1 * v1.y;
                av[12] += p0 * v1.z; av[13] += p1 * v1.z;
                av[14] += p0 * v1.w; av[15] += p1 * v1.w;
            }
            float s0, s1;
            reduce_scatter16(av, tj, s0, s1);
            SB[2 * chown][i0]     = s0 * rinv0;
            SB[2 * chown][i0 + 1] = s1 * rinv1;
        }

        // ---- phase 3b: sve partials (fp16 relv rows) + reduce-scatter ----
        {
            float av[16];
#pragma unroll
            for (int v = 0; v < 16; ++v) av[v] = 0.f;
#pragma unroll
            for (int cc = 0; cc < 8; ++cc) {
                int d = dbase + cc;
                uint4 rw = *(const uint4*)relV[d];
                const __half2* hp = (const __half2*)&rw;
                float2 va = __half22float2(hp[0]);
                float2 vb = __half22float2(hp[1]);
                float2 vc = __half22float2(hp[2]);
                float2 vd = __half22float2(hp[3]);
                if (cc <= 6) {
                    float p = P[6 - cc];
                    av[0] += p * va.x; av[2]  += p * va.y; av[4]  += p * vb.x; av[6]  += p * vb.y;
                    av[8] += p * vc.x; av[10] += p * vc.y; av[12] += p * vd.x; av[14] += p * vd.y;
                }
                if (cc >= 1) {
                    float p = P[7 + 7 - cc];
                    av[1] += p * va.x; av[3]  += p * va.y; av[5]  += p * vb.x; av[7]  += p * vb.y;
                    av[9] += p * vc.x; av[11] += p * vc.y; av[13] += p * vd.x; av[15] += p * vd.y;
                }
            }
            float s0, s1;
            reduce_scatter16(av, tj, s0, s1);
            SB[2 * chown + 1][i0]     = s0 * rinv0 * 0.1f;
            SB[2 * chown + 1][i0 + 1] = s1 * rinv1 * 0.1f;
        }
        __syncthreads();

        // ---- coalesced float4 write to g_so for this head ----
        {
            float4 v4 = *(const float4*)&SB[row_w][c4_w * 4];
            float* ob = g_so + (size_t)b * CH_STR + g * 16 * 56;
            *(float4*)&ob[row_w * 56 + c4_w * 4] = v4;
        }

        // ---- out stats: 128 threads = 16 rows x 8 lanes, butterfly reduce ----
        if (t < 128) {
            int row = t >> 3, sub = t & 7;
            float s1 = 0.f, s2 = 0.f;
#pragma unroll
            for (int e = 0; e < 7; ++e) {
                float v = SB[row][sub * 7 + e];
                s1 += v; s2 += v * v;
            }
#pragma unroll
            for (int m = 1; m < 8; m <<= 1) {
                s1 += __shfl_xor_sync(0xffffffffu, s1, m);
                s2 += __shfl_xor_sync(0xffffffffu, s2, m);
            }
            if (sub == 0) {
                atomicAdd(&g_osum[g * 16 + row], (double)s1);
                atomicAdd(&g_osq [g * 16 + row], (double)s2);
            }
        }
        __syncthreads();   // SB consumed; safe for next head
    }
}

// ---------------- K4: out BN (folded finalize) + pair-sum + layout ----------
__global__ void __launch_bounds__(256) k_out(float* __restrict__ out,
                                             const float* __restrict__ og,
                                             const float* __restrict__ ob) {
    __shared__ float sOs[128], sOo[128];
    {
        int o = threadIdx.x;
        if (o < 128) {
            double inv = 1.0 / NQKV;
            double m = g_osum[o] * inv;
            double v = g_osq[o] * inv - m * m;
            float sc = og[o] * rsqrtf((float)v + EPSBN);
            sOs[o] = sc;
            sOo[o] = ob[o] - (float)m * sc;
        }
    }
    __syncthreads();
    int idx = blockIdx.x * 256 + threadIdx.x;
    if (idx >= 1605632) return;
    int e  = idx * 4;
    int cp = e / XPLANE;
    int r  = e % XPLANE;
    int bq = r / 56, i = r % 56;
    const float* base = g_so + (size_t)bq * CH_STR + (2 * cp) * 56 + i;
    float4 s0 = *(const float4*)base;
    float4 s1 = *(const float4*)(base + 56);
    float sc0 = sOs[2 * cp], of0 = sOo[2 * cp];
    float sc1 = sOs[2 * cp + 1], of1 = sOo[2 * cp + 1];
    float4 o4;
    o4.x = s0.x * sc0 + of0 + s1.x * sc1 + of1;
    o4.y = s0.y * sc0 + of0 + s1.y * sc1 + of1;
    o4.z = s0.z * sc0 + of0 + s1.z * sc1 + of1;
    o4.w = s0.w * sc0 + of0 + s1.w * sc1 + of1;
    *(float4*)&out[e] = o4;
}

// ---------------- launch -----------------------------------------------------
extern "C" void kernel_launch(void* const* d_in, const int* in_sizes, int n_in,
                              void* d_out, int out_size) {
    const float* x        = (const float*)d_in[0];
    const float* w_qkv    = (const float*)d_in[1];
    const float* relative = (const float*)d_in[2];
    const float* qg       = (const float*)d_in[3];
    const float* qb       = (const float*)d_in[4];
    const float* sg       = (const float*)d_in[5];
    const float* sb       = (const float*)d_in[6];
    const float* og       = (const float*)d_in[7];
    const float* ob       = (const float*)d_in[8];
    float* out            = (float*)d_out;

    k_init <<<1, 256>>>(relative);
    k_qkv  <<<BTOT, 256>>>(x, w_qkv);
    k_mom  <<<BTOT, 256>>>(qg, qb);
    k_attn <<<BTOT, 224>>>(relative, qg, qb, sg, sb);
    k_out  <<<6272, 256>>>(out, og, ob);
}